// round 8
// baseline (speedup 1.0000x reference)
#include <cuda_runtime.h>
#include <stdint.h>

#define NVV 32
#define NRC 512
#define NRF 576
#define NPDF_RAYS 64
#define NB 128
#define NPTS_C 257
#define NPTS_F 289
#define NPF 288
#define NPDF_STEPS 32
#define HID 64
#define BINSZ 0.015f
#define TWOPI 6.283185307179586f
#define MINCOS 0.8660254037844386468f
#define TINYF 1.17549435e-38f

#define HIST_OFF  ((size_t)0)
#define SDF_OFF   ((size_t)4096)
#define NORM_OFF  ((size_t)5312512)
#define ALPHA_OFF ((size_t)21237760)
#define T_OFF     ((size_t)26546176)
#define W_OFF     ((size_t)31854592)
#define BA_OFF    ((size_t)37163008)
#define BW_OFF    ((size_t)39522304)
#define OP_OFF    ((size_t)41881600)
#define RP_OFF    ((size_t)41900032)
#define SP_OFF    ((size_t)41916416)

__device__ uint2 g_keys[12];
__device__ int   g_cnts[NVV * NRC];
__device__ int   g_idx[NVV * NPDF_RAYS];
__device__ float g_dir[NVV * NRF * 3];
__device__ float g_w[NVV * NRF];
__device__ int   g_uv[NVV * NRF];
__device__ float g_steps[(size_t)NVV * NRF * NPTS_F];
__device__ float g_radbins[(size_t)NVV * NRF * NB];

// ---------- threefry2x32 ----------
__device__ __forceinline__ void tfr(uint32_t& a, uint32_t& b, int r) {
    a += b; b = __funnelshift_l(b, b, r); b ^= a;
}
__device__ __forceinline__ void tf2(uint32_t k0, uint32_t k1, uint32_t x0, uint32_t x1,
                                    uint32_t& o0, uint32_t& o1) {
    uint32_t k2 = k0 ^ k1 ^ 0x1BD11BDAu;
    x0 += k0; x1 += k1;
    tfr(x0,x1,13); tfr(x0,x1,15); tfr(x0,x1,26); tfr(x0,x1,6);
    x0 += k1; x1 += k2 + 1u;
    tfr(x0,x1,17); tfr(x0,x1,29); tfr(x0,x1,16); tfr(x0,x1,24);
    x0 += k2; x1 += k0 + 2u;
    tfr(x0,x1,13); tfr(x0,x1,15); tfr(x0,x1,26); tfr(x0,x1,6);
    x0 += k0; x1 += k1 + 3u;
    tfr(x0,x1,17); tfr(x0,x1,29); tfr(x0,x1,16); tfr(x0,x1,24);
    x0 += k1; x1 += k2 + 4u;
    tfr(x0,x1,13); tfr(x0,x1,15); tfr(x0,x1,26); tfr(x0,x1,6);
    o0 = x0 + k2; o1 = x1 + k0 + 5u;
}
__device__ __forceinline__ uint2 tchild(uint2 k, uint32_t i) {
    uint32_t a, b; tf2(k.x, k.y, 0u, i, a, b); return make_uint2(a, b);
}
__device__ __forceinline__ float u01(uint2 k, uint32_t i) {
    uint32_t a, b; tf2(k.x, k.y, 0u, i, a, b);
    return __uint_as_float(((a ^ b) >> 9) | 0x3f800000u) - 1.0f;
}
__device__ __forceinline__ float gumbelf(uint2 k, uint32_t i) {
    float f = u01(k, i);
    float u = fmaxf(TINYF, f + TINYF);
    return -logf(-logf(u));
}

// ---------- XLA-matched math ----------
// XLA LogisticExpander: logistic(x) = 1 / (1 + exp(-x))  (exp = libdevice expf)
__device__ __forceinline__ float sigmf(float x) { return 1.0f / (1.0f + expf(-x)); }
// jax.nn.softplus = logaddexp(x, 0) = max(x,0) + log1p(exp(-|x|))
__device__ __forceinline__ float softplusf(float x) {
    return fmaxf(x, 0.0f) + log1pf(expf(-fabsf(x)));
}

// ---------- k0: keys + zero counts ----------
__global__ void k_init() {
    int t = threadIdx.x + blockIdx.x * blockDim.x;
    for (int i = t; i < NVV * NRC; i += gridDim.x * blockDim.x) g_cnts[i] = 0;
    if (t == 0) {
        uint2 root = make_uint2(0u, 42u);
        uint2 kc = tchild(root, 0), kf = tchild(root, 1);
        uint2 cA = tchild(kc, 0), cB = tchild(kc, 1);
        g_keys[0] = tchild(cA, 0); g_keys[1] = tchild(cA, 1); g_keys[2] = tchild(cB, 0);
        uint2 fA = tchild(kf, 0), fB = tchild(kf, 1);
        g_keys[3] = tchild(fA, 0); g_keys[4] = tchild(fA, 1); g_keys[5] = tchild(fA, 2);
        g_keys[6] = tchild(fA, 3); g_keys[7] = tchild(fA, 4);
        g_keys[8] = tchild(fB, 0); g_keys[9] = tchild(fB, 1); g_keys[10] = tchild(fB, 2);
    }
}

// ---------- k1: coarse ----------
__global__ void __launch_bounds__(128) k_coarse(
        const float* __restrict__ Rt, const float* __restrict__ W1,
        const float* __restrict__ b1, const float* __restrict__ w2,
        const float* __restrict__ b2v, float* __restrict__ out) {
    int r = blockIdx.x, v = blockIdx.y, t = threadIdx.x;
    __shared__ float st[NPTS_C], sd[NPTS_C], al[256];
    __shared__ float W1s[192], b1s[64], w2s[64], dirs[3], org[3];
    for (int i = t; i < 192; i += 128) W1s[i] = W1[i];
    for (int i = t; i < 64; i += 128) { b1s[i] = b1[i]; w2s[i] = w2[i]; }
    if (t == 0) {
        float ru  = ((float)(r / 8) + u01(g_keys[0], (uint32_t)(v * NRC + r))) / 64.0f;
        float rv  = ((float)(r % 8) + u01(g_keys[1], (uint32_t)(v * NRC + r))) / 8.0f;
        float phi = ru * TWOPI;
        float ct = rv * (1.0f - MINCOS) + MINCOS;
        float snt = sqrtf(fmaxf(1.0f - ct * ct, 0.0f));
        float d0 = snt * cosf(phi), d1 = snt * sinf(phi), d2 = ct;
        const float* Rv = Rt + v * 12;
        for (int i = 0; i < 3; i++) {
            dirs[i] = d0 * Rv[i*4] + d1 * Rv[i*4+1] + d2 * Rv[i*4+2];
            org[i]  = Rv[i*4+3];
        }
    }
    {
        float eta = u01(g_keys[2], (uint32_t)((v * NRC + r) * 128 + t)) * BINSZ;
        float left = BINSZ * (float)t;
        st[2*t] = left; st[2*t+1] = left + eta;
        if (t == 0) st[256] = BINSZ * 128.0f;
    }
    __syncthreads();
    float b2 = b2v[0];
    for (int k = t; k < NPTS_C; k += 128) {
        float s = st[k];
        float px = org[0] + s*dirs[0], py = org[1] + s*dirs[1], pz = org[2] + s*dirs[2];
        float acc = 0.0f;
        #pragma unroll 8
        for (int j = 0; j < HID; j++) {
            float z = fmaf(pz, W1s[128+j], fmaf(py, W1s[64+j], px * W1s[j])) + b1s[j];
            acc = fmaf(softplusf(z), w2s[j], acc);
        }
        sd[k] = acc + b2;
    }
    __syncthreads();
    for (int k = t; k < 256; k += 128) {
        float dl = st[k+1] - st[k];
        float ck = (sd[k+1] - sd[k]) / (dl + 1e-6f);
        float pv = (k > 0) ? (sd[k] - sd[k-1]) / ((st[k] - st[k-1]) + 1e-6f) : 0.0f;
        float c = fminf(fmaxf(fminf(pv, ck), -1000.0f), 0.0f);
        float ds = 0.5f * c * dl;
        float ms = 0.5f * (sd[k] + sd[k+1]);
        float pT = sigmf(64.0f * (ms - ds)), nT = sigmf(64.0f * (ms + ds));
        float mx = 0.5f*((org[0]+st[k]*dirs[0]) + (org[0]+st[k+1]*dirs[0]));
        float my = 0.5f*((org[1]+st[k]*dirs[1]) + (org[1]+st[k+1]*dirs[1]));
        float mz = 0.5f*((org[2]+st[k]*dirs[2]) + (org[2]+st[k+1]*dirs[2]));
        float nrm = sqrtf(mx*mx + my*my + mz*mz);
        float insf = (nrm < 1.0f && mz > 0.0f) ? 1.0f : 0.0f;
        al[k] = (1.0f - nT / (pT + 1e-6f)) * insf;
    }
    __syncthreads();
    if (t == 0) {
        float T = 1.0f, ray = 0.0f;
        float* spd = out + SP_OFF + (size_t)(v * NRC + r) * NB;
        for (int b = 0; b < NB; b++) {
            float w0 = al[2*b] * T;
            float o0 = 1.0f - al[2*b];   T *= o0*o0 + 1e-6f;
            float w1 = al[2*b+1] * T;
            float o1 = 1.0f - al[2*b+1]; T *= o1*o1 + 1e-6f;
            float sp = w0 + w1; spd[b] = sp; ray += sp;
        }
        out[RP_OFF + (size_t)(v * NRC + r)] = ray;
    }
}

// ---------- k2: ray categorical ----------
__global__ void __launch_bounds__(128) k_ray_idx(const float* __restrict__ out) {
    int p = blockIdx.x, v = blockIdx.y, t = threadIdx.x;
    const float* rp = out + RP_OFF + (size_t)v * NRC;
    uint2 kg = g_keys[5];
    float best = -3.4e38f; int bi = 1 << 30;
    for (int s = t; s < NRC; s += 128) {
        float val = gumbelf(kg, (uint32_t)((p * NVV + v) * NRC + s)) + logf(rp[s] + 1e-6f);
        if (val > best) { best = val; bi = s; }
    }
    __shared__ float bv[128]; __shared__ int bx[128];
    bv[t] = best; bx[t] = bi; __syncthreads();
    for (int s = 64; s > 0; s >>= 1) {
        if (t < s) {
            if (bv[t+s] > bv[t] || (bv[t+s] == bv[t] && bx[t+s] < bx[t])) {
                bv[t] = bv[t+s]; bx[t] = bx[t+s];
            }
        }
        __syncthreads();
    }
    if (t == 0) {
        g_idx[v * NPDF_RAYS + p] = bx[0];
        atomicAdd(&g_cnts[v * NRC + bx[0]], 1);
    }
}

// ---------- k3: fine ray gen ----------
__global__ void __launch_bounds__(NRF) k_fine_rays(const float* __restrict__ Rt) {
    int v = blockIdx.x, r = threadIdx.x;
    int uv; float U1, U2;
    if (r < NRC) {
        uv = r;
        U1 = u01(g_keys[3], (uint32_t)(v * NRC + r));
        U2 = u01(g_keys[4], (uint32_t)(v * NRC + r));
    } else {
        int p = r - NRC;
        uv = g_idx[v * NPDF_RAYS + p];
        U1 = u01(g_keys[6], (uint32_t)(v * NPDF_RAYS + p));
        U2 = u01(g_keys[7], (uint32_t)(v * NPDF_RAYS + p));
    }
    float ru  = ((float)(uv / 8) + U1) / 64.0f;
    float rv  = ((float)(uv % 8) + U2) / 8.0f;
    float phi = ru * TWOPI;
    float ct = rv * (1.0f - MINCOS) + MINCOS;
    float snt = sqrtf(fmaxf(1.0f - ct * ct, 0.0f));
    float d0 = snt * cosf(phi), d1 = snt * sinf(phi), d2 = ct;
    const float* Rv = Rt + v * 12;
    size_t ray = (size_t)v * NRF + r;
    for (int i = 0; i < 3; i++)
        g_dir[ray*3+i] = d0*Rv[i*4] + d1*Rv[i*4+1] + d2*Rv[i*4+2];
    int cnt = g_cnts[v * NRC + uv];
    float sang = 2.0f * 3.14159265358979323846f * (1.0f - MINCOS);
    g_w[ray] = (1.0f / (((float)cnt + 1.0f) * 512.0f)) * ct * sang;
    g_uv[ray] = uv;
}

// ---------- k4: fine step sampling ----------
__global__ void __launch_bounds__(128) k_fine_steps(const float* __restrict__ out) {
    int r = blockIdx.x, v = blockIdx.y, t = threadIdx.x;
    __shared__ float logit[NB], base[NPTS_C], ex[NPDF_STEPS];
    __shared__ int sbidx[NPDF_STEPS];
    __shared__ float wv[4]; __shared__ int wi[4];
    int uv = g_uv[(size_t)v * NRF + r];
    logit[t] = logf(out[SP_OFF + (size_t)(v * NRC + uv) * NB + t] + 1e-6f);
    {
        float eta = u01(g_keys[8], (uint32_t)((v * NRF + r) * 128 + t)) * BINSZ;
        float left = BINSZ * (float)t;
        base[2*t] = left; base[2*t+1] = left + eta;
        if (t == 0) base[256] = BINSZ * 128.0f;
    }
    __syncthreads();
    uint2 kg = g_keys[9];
    int lane = t & 31, wid = t >> 5;
    for (int p = 0; p < NPDF_STEPS; p++) {
        float val = gumbelf(kg, (uint32_t)(((p * NVV + v) * NRF + r) * 128 + t)) + logit[t];
        int idx = t;
        for (int o = 16; o > 0; o >>= 1) {
            float v2 = __shfl_down_sync(0xffffffffu, val, o);
            int   i2 = __shfl_down_sync(0xffffffffu, idx, o);
            if (v2 > val || (v2 == val && i2 < idx)) { val = v2; idx = i2; }
        }
        if (lane == 0) { wv[wid] = val; wi[wid] = idx; }
        __syncthreads();
        if (t == 0) {
            float bb = wv[0]; int bi = wi[0];
            for (int q = 1; q < 4; q++)
                if (wv[q] > bb || (wv[q] == bb && wi[q] < bi)) { bb = wv[q]; bi = wi[q]; }
            sbidx[p] = bi;
        }
        __syncthreads();
    }
    if (t < NPDF_STEPS)
        ex[t] = BINSZ * (float)sbidx[t] + u01(g_keys[10], (uint32_t)((v * NRF + r) * 32 + t)) * BINSZ;
    __syncthreads();
    if (t == 0) {
        for (int i = 1; i < NPDF_STEPS; i++) {
            float x = ex[i]; int j = i - 1;
            while (j >= 0 && ex[j] > x) { ex[j+1] = ex[j]; j--; }
            ex[j+1] = x;
        }
    }
    __syncthreads();
    float* dst = g_steps + ((size_t)v * NRF + r) * NPTS_F;
    for (int k = t; k < NPTS_C; k += 128) {
        float x = base[k]; int lo = 0, hi = NPDF_STEPS;
        while (lo < hi) { int m = (lo+hi)>>1; if (ex[m] < x) lo = m+1; else hi = m; }
        dst[k + lo] = x;
    }
    if (t < NPDF_STEPS) {
        float x = ex[t]; int lo = 0, hi = NPTS_C;
        while (lo < hi) { int m = (lo+hi)>>1; if (base[m] <= x) lo = m+1; else hi = m; }
        dst[t + lo] = x;
    }
}

// ---------- k5: fine main ----------
__global__ void __launch_bounds__(96) k_fine_main(
        const float* __restrict__ Rt, const float* __restrict__ W1,
        const float* __restrict__ b1, const float* __restrict__ w2,
        const float* __restrict__ b2v, const float* __restrict__ inv_sv,
        const float* __restrict__ rhov, float* __restrict__ out) {
    int r = blockIdx.x, v = blockIdx.y, t = threadIdx.x;
    __shared__ float W1s[192], b1s[64], w2s[64];
    __shared__ float al[NPF], rf[NPF], Ts[NPF];
    __shared__ int bvd[NPF];
    __shared__ float ba[NB], bw[NB], br[NB];
    for (int i = t; i < 192; i += 96) W1s[i] = W1[i];
    for (int i = t; i < 64; i += 96) { b1s[i] = b1[i]; w2s[i] = w2[i]; }
    for (int i = t; i < NB; i += 96) { ba[i] = 0.0f; bw[i] = 0.0f; br[i] = 0.0f; }
    size_t ray = (size_t)v * NRF + r;
    const float* se = g_steps + ray * NPTS_F;
    float dx = g_dir[ray*3], dy = g_dir[ray*3+1], dz = g_dir[ray*3+2];
    const float* Rv = Rt + v * 12;
    float ox = Rv[3], oy = Rv[7], oz = Rv[11];
    float b2 = b2v[0], inv_s = inv_sv[0], rho = rhov[0];
    __syncthreads();
    for (int k = t; k < NPF; k += 96) {
        float s0 = se[k], s1 = se[k+1];
        float delta = s1 - s0, sm = 0.5f * (s1 + s0);
        float px = ox + sm*dx, py = oy + sm*dy, pz = oz + sm*dz;
        float nrm = sqrtf(px*px + py*py + pz*pz);
        float insf = (nrm < 1.0f && pz > 0.0f) ? 1.0f : 0.0f;
        float sdf = 0.0f, n0 = 0.0f, n1 = 0.0f, n2 = 0.0f;
        #pragma unroll 8
        for (int j = 0; j < HID; j++) {
            float w0j = W1s[j], w1j = W1s[64+j], w2j = W1s[128+j];
            float z = fmaf(pz, w2j, fmaf(py, w1j, px * w0j)) + b1s[j];
            sdf = fmaf(softplusf(z), w2s[j], sdf);
            float sg = sigmf(z) * w2s[j];
            n0 = fmaf(sg, w0j, n0); n1 = fmaf(sg, w1j, n1); n2 = fmaf(sg, w2j, n2);
        }
        sdf = (sdf + b2) * insf; n0 *= insf; n1 *= insf; n2 *= insf;
        out[SDF_OFF + ray*NPF + k] = sdf;
        out[NORM_OFF + (ray*NPF + k)*3 + 0] = n0;
        out[NORM_OFF + (ray*NPF + k)*3 + 1] = n1;
        out[NORM_OFF + (ray*NPF + k)*3 + 2] = n2;
        float cs = dx*n0 + dy*n1 + dz*n2;
        float ac = -fmaxf(fmaf(cs, -0.5f, 0.5f), 0.0f);
        float ds = 0.5f * ac * delta;
        float pT = sigmf(inv_s * (sdf - ds)), nT = sigmf(inv_s * (sdf + ds));
        float a = (1.0f - nT / (pT + 1e-6f)) * insf;
        out[ALPHA_OFF + ray*NPF + k] = a;
        al[k] = a;
        rf[k] = rho * (-ac / (sm*sm + 1e-6f));
        int bi = (int)floorf(sm / BINSZ);
        bi = max(0, min(NB - 1, bi));
        bool valid = (sm > (float)bi * BINSZ) && (sm < (float)(bi+1) * BINSZ);
        bvd[k] = valid ? bi : -1;
    }
    __syncthreads();
    if (t == 0) {
        float T = 1.0f, opac = 0.0f;
        for (int k = 0; k < NPF; k++) {
            Ts[k] = T;
            float wk = al[k] * T;
            int b = bvd[k];
            if (b >= 0) { ba[b] += al[k]; bw[b] += wk; br[b] += wk * rf[k]; opac += wk; }
            float om = 1.0f - al[k];
            T *= om * om;
        }
        out[OP_OFF + ray] = opac;
    }
    __syncthreads();
    for (int k = t; k < NPF; k += 96) {
        out[T_OFF + ray*NPF + k] = Ts[k];
        out[W_OFF + ray*NPF + k] = al[k] * Ts[k];
    }
    for (int b = t; b < NB; b += 96) {
        out[BA_OFF + ray*NB + b] = ba[b];
        out[BW_OFF + ray*NB + b] = bw[b];
        g_radbins[ray*NB + b] = br[b];
    }
}

// ---------- k6: hists ----------
__global__ void __launch_bounds__(NB) k_hists(float* __restrict__ out) {
    int v = blockIdx.x, b = threadIdx.x;
    float acc = 0.0f;
    for (int r = 0; r < NRF; r++)
        acc += g_radbins[((size_t)v * NRF + r) * NB + b] * g_w[v * NRF + r];
    out[HIST_OFF + (size_t)v * NB + b] = acc;
}

extern "C" void kernel_launch(void* const* d_in, const int* in_sizes, int n_in,
                              void* d_out, int out_size) {
    const float* Rt = (const float*)d_in[0];
    const float* W1 = (const float*)d_in[1];
    const float* b1 = (const float*)d_in[2];
    const float* w2 = (const float*)d_in[3];
    const float* b2 = (const float*)d_in[4];
    const float* inv_s = (const float*)d_in[5];
    const float* rho = (const float*)d_in[6];
    float* out = (float*)d_out;
    k_init<<<64, 256>>>();
    k_coarse<<<dim3(NRC, NVV), 128>>>(Rt, W1, b1, w2, b2, out);
    k_ray_idx<<<dim3(NPDF_RAYS, NVV), 128>>>(out);
    k_fine_rays<<<NVV, NRF>>>(Rt);
    k_fine_steps<<<dim3(NRF, NVV), 128>>>(out);
    k_fine_main<<<dim3(NRF, NVV), 96>>>(Rt, W1, b1, w2, b2, inv_s, rho, out);
    k_hists<<<NVV, NB>>>(out);
}

// round 9
// speedup vs baseline: 1.1127x; 1.1127x over previous
#include <cuda_runtime.h>
#include <stdint.h>

#define NVV 32
#define NRC 512
#define NRF 576
#define NPDF_RAYS 64
#define NB 128
#define NPTS_C 257
#define NPTS_F 289
#define NPF 288
#define NPDF_STEPS 32
#define HID 64
#define BINSZ 0.015f
#define TWOPI 6.283185307179586f
#define MINCOS 0.8660254037844386468f
#define TINYF 1.17549435e-38f

#define HIST_OFF  ((size_t)0)
#define SDF_OFF   ((size_t)4096)
#define NORM_OFF  ((size_t)5312512)
#define ALPHA_OFF ((size_t)21237760)
#define T_OFF     ((size_t)26546176)
#define W_OFF     ((size_t)31854592)
#define BA_OFF    ((size_t)37163008)
#define BW_OFF    ((size_t)39522304)
#define OP_OFF    ((size_t)41881600)
#define RP_OFF    ((size_t)41900032)
#define SP_OFF    ((size_t)41916416)

__device__ uint2 g_keys[12];
__device__ int   g_cnts[NVV * NRC];
__device__ int   g_idx[NVV * NPDF_RAYS];
__device__ float g_dir[NVV * NRF * 3];
__device__ float g_w[NVV * NRF];
__device__ int   g_uv[NVV * NRF];
__device__ float g_steps[(size_t)NVV * NRF * NPTS_F];
__device__ float g_radbins[(size_t)NVV * NRF * NB];

// ---------- threefry2x32 ----------
__device__ __forceinline__ void tfr(uint32_t& a, uint32_t& b, int r) {
    a += b; b = __funnelshift_l(b, b, r); b ^= a;
}
__device__ __forceinline__ void tf2(uint32_t k0, uint32_t k1, uint32_t x0, uint32_t x1,
                                    uint32_t& o0, uint32_t& o1) {
    uint32_t k2 = k0 ^ k1 ^ 0x1BD11BDAu;
    x0 += k0; x1 += k1;
    tfr(x0,x1,13); tfr(x0,x1,15); tfr(x0,x1,26); tfr(x0,x1,6);
    x0 += k1; x1 += k2 + 1u;
    tfr(x0,x1,17); tfr(x0,x1,29); tfr(x0,x1,16); tfr(x0,x1,24);
    x0 += k2; x1 += k0 + 2u;
    tfr(x0,x1,13); tfr(x0,x1,15); tfr(x0,x1,26); tfr(x0,x1,6);
    x0 += k0; x1 += k1 + 3u;
    tfr(x0,x1,17); tfr(x0,x1,29); tfr(x0,x1,16); tfr(x0,x1,24);
    x0 += k1; x1 += k2 + 4u;
    tfr(x0,x1,13); tfr(x0,x1,15); tfr(x0,x1,26); tfr(x0,x1,6);
    o0 = x0 + k2; o1 = x1 + k0 + 5u;
}
__device__ __forceinline__ uint2 tchild(uint2 k, uint32_t i) {
    uint32_t a, b; tf2(k.x, k.y, 0u, i, a, b); return make_uint2(a, b);
}
__device__ __forceinline__ float u01(uint2 k, uint32_t i) {
    uint32_t a, b; tf2(k.x, k.y, 0u, i, a, b);
    return __uint_as_float(((a ^ b) >> 9) | 0x3f800000u) - 1.0f;
}
__device__ __forceinline__ float gumbelf(uint2 k, uint32_t i) {
    float f = u01(k, i);
    float u = fmaxf(TINYF, f + TINYF);
    return -logf(-logf(u));
}

// ---------- XLA-matched math ----------
// Exact reference form (used where values feed categorical argmax / transmittance):
__device__ __forceinline__ float sigmf(float x) { return 1.0f / (1.0f + expf(-x)); }
__device__ __forceinline__ float softplusf(float x) {
    return fmaxf(x, 0.0f) + log1pf(expf(-fabsf(x)));
}

// ---------- k0: keys + zero counts ----------
__global__ void k_init() {
    int t = threadIdx.x + blockIdx.x * blockDim.x;
    for (int i = t; i < NVV * NRC; i += gridDim.x * blockDim.x) g_cnts[i] = 0;
    if (t == 0) {
        uint2 root = make_uint2(0u, 42u);
        uint2 kc = tchild(root, 0), kf = tchild(root, 1);
        uint2 cA = tchild(kc, 0), cB = tchild(kc, 1);
        g_keys[0] = tchild(cA, 0); g_keys[1] = tchild(cA, 1); g_keys[2] = tchild(cB, 0);
        uint2 fA = tchild(kf, 0), fB = tchild(kf, 1);
        g_keys[3] = tchild(fA, 0); g_keys[4] = tchild(fA, 1); g_keys[5] = tchild(fA, 2);
        g_keys[6] = tchild(fA, 3); g_keys[7] = tchild(fA, 4);
        g_keys[8] = tchild(fB, 0); g_keys[9] = tchild(fB, 1); g_keys[10] = tchild(fB, 2);
    }
}

// ---------- k1: coarse (numerics untouched — feeds both argmaxes) ----------
__global__ void __launch_bounds__(128) k_coarse(
        const float* __restrict__ Rt, const float* __restrict__ W1,
        const float* __restrict__ b1, const float* __restrict__ w2,
        const float* __restrict__ b2v, float* __restrict__ out) {
    int r = blockIdx.x, v = blockIdx.y, t = threadIdx.x;
    __shared__ float st[NPTS_C], sd[NPTS_C], al[256];
    __shared__ float W1s[192], b1s[64], w2s[64], dirs[3], org[3];
    for (int i = t; i < 192; i += 128) W1s[i] = W1[i];
    for (int i = t; i < 64; i += 128) { b1s[i] = b1[i]; w2s[i] = w2[i]; }
    if (t == 0) {
        float ru  = ((float)(r / 8) + u01(g_keys[0], (uint32_t)(v * NRC + r))) / 64.0f;
        float rv  = ((float)(r % 8) + u01(g_keys[1], (uint32_t)(v * NRC + r))) / 8.0f;
        float phi = ru * TWOPI;
        float ct = rv * (1.0f - MINCOS) + MINCOS;
        float snt = sqrtf(fmaxf(1.0f - ct * ct, 0.0f));
        float d0 = snt * cosf(phi), d1 = snt * sinf(phi), d2 = ct;
        const float* Rv = Rt + v * 12;
        for (int i = 0; i < 3; i++) {
            dirs[i] = d0 * Rv[i*4] + d1 * Rv[i*4+1] + d2 * Rv[i*4+2];
            org[i]  = Rv[i*4+3];
        }
    }
    {
        float eta = u01(g_keys[2], (uint32_t)((v * NRC + r) * 128 + t)) * BINSZ;
        float left = BINSZ * (float)t;
        st[2*t] = left; st[2*t+1] = left + eta;
        if (t == 0) st[256] = BINSZ * 128.0f;
    }
    __syncthreads();
    float b2 = b2v[0];
    for (int k = t; k < NPTS_C; k += 128) {
        float s = st[k];
        float px = org[0] + s*dirs[0], py = org[1] + s*dirs[1], pz = org[2] + s*dirs[2];
        float acc = 0.0f;
        #pragma unroll 8
        for (int j = 0; j < HID; j++) {
            float z = fmaf(pz, W1s[128+j], fmaf(py, W1s[64+j], px * W1s[j])) + b1s[j];
            acc = fmaf(softplusf(z), w2s[j], acc);
        }
        sd[k] = acc + b2;
    }
    __syncthreads();
    for (int k = t; k < 256; k += 128) {
        float dl = st[k+1] - st[k];
        float ck = (sd[k+1] - sd[k]) / (dl + 1e-6f);
        float pv = (k > 0) ? (sd[k] - sd[k-1]) / ((st[k] - st[k-1]) + 1e-6f) : 0.0f;
        float c = fminf(fmaxf(fminf(pv, ck), -1000.0f), 0.0f);
        float ds = 0.5f * c * dl;
        float ms = 0.5f * (sd[k] + sd[k+1]);
        float pT = sigmf(64.0f * (ms - ds)), nT = sigmf(64.0f * (ms + ds));
        float mx = 0.5f*((org[0]+st[k]*dirs[0]) + (org[0]+st[k+1]*dirs[0]));
        float my = 0.5f*((org[1]+st[k]*dirs[1]) + (org[1]+st[k+1]*dirs[1]));
        float mz = 0.5f*((org[2]+st[k]*dirs[2]) + (org[2]+st[k+1]*dirs[2]));
        float nrm = sqrtf(mx*mx + my*my + mz*mz);
        float insf = (nrm < 1.0f && mz > 0.0f) ? 1.0f : 0.0f;
        al[k] = (1.0f - nT / (pT + 1e-6f)) * insf;
    }
    __syncthreads();
    if (t == 0) {
        float T = 1.0f, ray = 0.0f;
        float* spd = out + SP_OFF + (size_t)(v * NRC + r) * NB;
        for (int b = 0; b < NB; b++) {
            float w0 = al[2*b] * T;
            float o0 = 1.0f - al[2*b];   T *= o0*o0 + 1e-6f;
            float w1 = al[2*b+1] * T;
            float o1 = 1.0f - al[2*b+1]; T *= o1*o1 + 1e-6f;
            float sp = w0 + w1; spd[b] = sp; ray += sp;
        }
        out[RP_OFF + (size_t)(v * NRC + r)] = ray;
    }
}

// ---------- k2: ray categorical ----------
__global__ void __launch_bounds__(128) k_ray_idx(const float* __restrict__ out) {
    int p = blockIdx.x, v = blockIdx.y, t = threadIdx.x;
    const float* rp = out + RP_OFF + (size_t)v * NRC;
    uint2 kg = g_keys[5];
    float best = -3.4e38f; int bi = 1 << 30;
    for (int s = t; s < NRC; s += 128) {
        float val = gumbelf(kg, (uint32_t)((p * NVV + v) * NRC + s)) + logf(rp[s] + 1e-6f);
        if (val > best || (val == best && s < bi)) { best = val; bi = s; }
    }
    __shared__ float bv[128]; __shared__ int bx[128];
    bv[t] = best; bx[t] = bi; __syncthreads();
    for (int s = 64; s > 0; s >>= 1) {
        if (t < s) {
            if (bv[t+s] > bv[t] || (bv[t+s] == bv[t] && bx[t+s] < bx[t])) {
                bv[t] = bv[t+s]; bx[t] = bx[t+s];
            }
        }
        __syncthreads();
    }
    if (t == 0) {
        g_idx[v * NPDF_RAYS + p] = bx[0];
        atomicAdd(&g_cnts[v * NRC + bx[0]], 1);
    }
}

// ---------- k3: fine ray gen ----------
__global__ void __launch_bounds__(NRF) k_fine_rays(const float* __restrict__ Rt) {
    int v = blockIdx.x, r = threadIdx.x;
    int uv; float U1, U2;
    if (r < NRC) {
        uv = r;
        U1 = u01(g_keys[3], (uint32_t)(v * NRC + r));
        U2 = u01(g_keys[4], (uint32_t)(v * NRC + r));
    } else {
        int p = r - NRC;
        uv = g_idx[v * NPDF_RAYS + p];
        U1 = u01(g_keys[6], (uint32_t)(v * NPDF_RAYS + p));
        U2 = u01(g_keys[7], (uint32_t)(v * NPDF_RAYS + p));
    }
    float ru  = ((float)(uv / 8) + U1) / 64.0f;
    float rv  = ((float)(uv % 8) + U2) / 8.0f;
    float phi = ru * TWOPI;
    float ct = rv * (1.0f - MINCOS) + MINCOS;
    float snt = sqrtf(fmaxf(1.0f - ct * ct, 0.0f));
    float d0 = snt * cosf(phi), d1 = snt * sinf(phi), d2 = ct;
    const float* Rv = Rt + v * 12;
    size_t ray = (size_t)v * NRF + r;
    for (int i = 0; i < 3; i++)
        g_dir[ray*3+i] = d0*Rv[i*4] + d1*Rv[i*4+1] + d2*Rv[i*4+2];
    int cnt = g_cnts[v * NRC + uv];
    float sang = 2.0f * 3.14159265358979323846f * (1.0f - MINCOS);
    g_w[ray] = (1.0f / (((float)cnt + 1.0f) * 512.0f)) * ct * sang;
    g_uv[ray] = uv;
}

// ---------- k4: fine step sampling — warp-per-draw, barrier-free hot loop ----------
__global__ void __launch_bounds__(128) k_fine_steps(const float* __restrict__ out) {
    int r = blockIdx.x, v = blockIdx.y, t = threadIdx.x;
    int lane = t & 31, wid = t >> 5;
    __shared__ float logit[NB], base[NPTS_C], ex[NPDF_STEPS], exs[NPDF_STEPS];
    __shared__ int sbidx[NPDF_STEPS];
    int uv = g_uv[(size_t)v * NRF + r];
    logit[t] = logf(out[SP_OFF + (size_t)(v * NRC + uv) * NB + t] + 1e-6f);
    {
        float eta = u01(g_keys[8], (uint32_t)((v * NRF + r) * 128 + t)) * BINSZ;
        float left = BINSZ * (float)t;
        base[2*t] = left; base[2*t+1] = left + eta;
        if (t == 0) base[256] = BINSZ * 128.0f;
    }
    __syncthreads();
    uint2 kg = g_keys[9];
    uint32_t ibase = (uint32_t)((uint32_t)v * NRF + (uint32_t)r) * 128u;
    // 4 warps x 8 draws; each draw fully in-warp (no block barriers)
    for (int p = wid; p < NPDF_STEPS; p += 4) {
        uint32_t doff = (uint32_t)p * (uint32_t)(NVV * NRF) * 128u + ibase;
        float best = -3.4e38f; int bi = 1 << 30;
        #pragma unroll
        for (int q = 0; q < 4; q++) {
            int bin = lane + q * 32;
            float val = gumbelf(kg, doff + (uint32_t)bin) + logit[bin];
            if (val > best || (val == best && bin < bi)) { best = val; bi = bin; }
        }
        #pragma unroll
        for (int o = 16; o > 0; o >>= 1) {
            float v2 = __shfl_down_sync(0xffffffffu, best, o);
            int   i2 = __shfl_down_sync(0xffffffffu, bi, o);
            if (v2 > best || (v2 == best && i2 < bi)) { best = v2; bi = i2; }
        }
        if (lane == 0) sbidx[p] = bi;
    }
    __syncthreads();
    if (t < NPDF_STEPS)
        ex[t] = BINSZ * (float)sbidx[t] + u01(g_keys[10], (uint32_t)((v * NRF + r) * 32 + t)) * BINSZ;
    __syncthreads();
    if (t < NPDF_STEPS) {   // parallel rank sort of 32 extras
        float x = ex[t]; int rank = 0;
        #pragma unroll
        for (int j = 0; j < NPDF_STEPS; j++) {
            float y = ex[j];
            rank += (y < x) || (y == x && j < t);
        }
        exs[rank] = x;
    }
    __syncthreads();
    float* dst = g_steps + ((size_t)v * NRF + r) * NPTS_F;
    for (int k = t; k < NPTS_C; k += 128) {
        float x = base[k]; int lo = 0, hi = NPDF_STEPS;
        while (lo < hi) { int m = (lo+hi)>>1; if (exs[m] < x) lo = m+1; else hi = m; }
        dst[k + lo] = x;
    }
    if (t < NPDF_STEPS) {
        float x = exs[t]; int lo = 0, hi = NPTS_C;
        while (lo < hi) { int m = (lo+hi)>>1; if (base[m] <= x) lo = m+1; else hi = m; }
        dst[t + lo] = x;
    }
}

// ---------- k5: fine main — shared expf between softplus & sigmoid ----------
__global__ void __launch_bounds__(96) k_fine_main(
        const float* __restrict__ Rt, const float* __restrict__ W1,
        const float* __restrict__ b1, const float* __restrict__ w2,
        const float* __restrict__ b2v, const float* __restrict__ inv_sv,
        const float* __restrict__ rhov, float* __restrict__ out) {
    int r = blockIdx.x, v = blockIdx.y, t = threadIdx.x;
    __shared__ float W1s[192], b1s[64], w2s[64];
    __shared__ float al[NPF], rf[NPF], Ts[NPF];
    __shared__ int bvd[NPF];
    __shared__ float ba[NB], bw[NB], br[NB];
    for (int i = t; i < 192; i += 96) W1s[i] = W1[i];
    for (int i = t; i < 64; i += 96) { b1s[i] = b1[i]; w2s[i] = w2[i]; }
    for (int i = t; i < NB; i += 96) { ba[i] = 0.0f; bw[i] = 0.0f; br[i] = 0.0f; }
    size_t ray = (size_t)v * NRF + r;
    const float* se = g_steps + ray * NPTS_F;
    float dx = g_dir[ray*3], dy = g_dir[ray*3+1], dz = g_dir[ray*3+2];
    const float* Rv = Rt + v * 12;
    float ox = Rv[3], oy = Rv[7], oz = Rv[11];
    float b2 = b2v[0], inv_s = inv_sv[0], rho = rhov[0];
    __syncthreads();
    for (int k = t; k < NPF; k += 96) {
        float s0 = se[k], s1 = se[k+1];
        float delta = s1 - s0, sm = 0.5f * (s1 + s0);
        float px = ox + sm*dx, py = oy + sm*dy, pz = oz + sm*dz;
        float nrm = sqrtf(px*px + py*py + pz*pz);
        float insf = (nrm < 1.0f && pz > 0.0f) ? 1.0f : 0.0f;
        float sdf = 0.0f, n0 = 0.0f, n1 = 0.0f, n2 = 0.0f;
        #pragma unroll 8
        for (int j = 0; j < HID; j++) {
            float w0j = W1s[j], w1j = W1s[64+j], w2j = W1s[128+j];
            float z = fmaf(pz, w2j, fmaf(py, w1j, px * w0j)) + b1s[j];
            float tE = expf(-fabsf(z));           // one expf for both
            sdf = fmaf(fmaxf(z, 0.0f) + log1pf(tE), w2s[j], sdf);
            float inv = 1.0f / (1.0f + tE);
            float sg = ((z >= 0.0f) ? inv : tE * inv) * w2s[j];
            n0 = fmaf(sg, w0j, n0); n1 = fmaf(sg, w1j, n1); n2 = fmaf(sg, w2j, n2);
        }
        sdf = (sdf + b2) * insf; n0 *= insf; n1 *= insf; n2 *= insf;
        out[SDF_OFF + ray*NPF + k] = sdf;
        out[NORM_OFF + (ray*NPF + k)*3 + 0] = n0;
        out[NORM_OFF + (ray*NPF + k)*3 + 1] = n1;
        out[NORM_OFF + (ray*NPF + k)*3 + 2] = n2;
        float cs = dx*n0 + dy*n1 + dz*n2;
        float ac = -fmaxf(fmaf(cs, -0.5f, 0.5f), 0.0f);
        float ds = 0.5f * ac * delta;
        float pT = sigmf(inv_s * (sdf - ds)), nT = sigmf(inv_s * (sdf + ds));
        float a = (1.0f - nT / (pT + 1e-6f)) * insf;
        out[ALPHA_OFF + ray*NPF + k] = a;
        al[k] = a;
        rf[k] = rho * (-ac / (sm*sm + 1e-6f));
        int bi = (int)floorf(sm / BINSZ);
        bi = max(0, min(NB - 1, bi));
        bool valid = (sm > (float)bi * BINSZ) && (sm < (float)(bi+1) * BINSZ);
        bvd[k] = valid ? bi : -1;
    }
    __syncthreads();
    if (t == 0) {
        float T = 1.0f, opac = 0.0f;
        for (int k = 0; k < NPF; k++) {
            Ts[k] = T;
            float wk = al[k] * T;
            int b = bvd[k];
            if (b >= 0) { ba[b] += al[k]; bw[b] += wk; br[b] += wk * rf[k]; opac += wk; }
            float om = 1.0f - al[k];
            T *= om * om;
        }
        out[OP_OFF + ray] = opac;
    }
    __syncthreads();
    for (int k = t; k < NPF; k += 96) {
        out[T_OFF + ray*NPF + k] = Ts[k];
        out[W_OFF + ray*NPF + k] = al[k] * Ts[k];
    }
    for (int b = t; b < NB; b += 96) {
        out[BA_OFF + ray*NB + b] = ba[b];
        out[BW_OFF + ray*NB + b] = bw[b];
        g_radbins[ray*NB + b] = br[b];
    }
}

// ---------- k6: hists ----------
__global__ void __launch_bounds__(NB) k_hists(float* __restrict__ out) {
    int v = blockIdx.x, b = threadIdx.x;
    float acc = 0.0f;
    for (int r = 0; r < NRF; r++)
        acc += g_radbins[((size_t)v * NRF + r) * NB + b] * g_w[v * NRF + r];
    out[HIST_OFF + (size_t)v * NB + b] = acc;
}

extern "C" void kernel_launch(void* const* d_in, const int* in_sizes, int n_in,
                              void* d_out, int out_size) {
    const float* Rt = (const float*)d_in[0];
    const float* W1 = (const float*)d_in[1];
    const float* b1 = (const float*)d_in[2];
    const float* w2 = (const float*)d_in[3];
    const float* b2 = (const float*)d_in[4];
    const float* inv_s = (const float*)d_in[5];
    const float* rho = (const float*)d_in[6];
    float* out = (float*)d_out;
    k_init<<<64, 256>>>();
    k_coarse<<<dim3(NRC, NVV), 128>>>(Rt, W1, b1, w2, b2, out);
    k_ray_idx<<<dim3(NPDF_RAYS, NVV), 128>>>(out);
    k_fine_rays<<<NVV, NRF>>>(Rt);
    k_fine_steps<<<dim3(NRF, NVV), 128>>>(out);
    k_fine_main<<<dim3(NRF, NVV), 96>>>(Rt, W1, b1, w2, b2, inv_s, rho, out);
    k_hists<<<NVV, NB>>>(out);
}

// round 10
// speedup vs baseline: 1.7271x; 1.5521x over previous
#include <cuda_runtime.h>
#include <stdint.h>

#define NVV 32
#define NRC 512
#define NRF 576
#define NPDF_RAYS 64
#define NB 128
#define NPTS_C 257
#define NPTS_F 289
#define NPF 288
#define NPDF_STEPS 32
#define HID 64
#define BINSZ 0.015f
#define TWOPI 6.283185307179586f
#define MINCOS 0.8660254037844386468f
#define TINYF 1.17549435e-38f

#define HIST_OFF  ((size_t)0)
#define SDF_OFF   ((size_t)4096)
#define NORM_OFF  ((size_t)5312512)
#define ALPHA_OFF ((size_t)21237760)
#define T_OFF     ((size_t)26546176)
#define W_OFF     ((size_t)31854592)
#define BA_OFF    ((size_t)37163008)
#define BW_OFF    ((size_t)39522304)
#define OP_OFF    ((size_t)41881600)
#define RP_OFF    ((size_t)41900032)
#define SP_OFF    ((size_t)41916416)

__device__ uint2 g_keys[12];
__device__ int   g_cnts[NVV * NRC];
__device__ int   g_idx[NVV * NPDF_RAYS];
__device__ float g_dir[NVV * NRF * 3];
__device__ float g_w[NVV * NRF];
__device__ int   g_uv[NVV * NRF];
__device__ float g_steps[(size_t)NVV * NRF * NPTS_F];
__device__ float g_radbins[(size_t)NVV * NRF * NB];

// ---------- threefry2x32 ----------
__device__ __forceinline__ void tfr(uint32_t& a, uint32_t& b, int r) {
    a += b; b = __funnelshift_l(b, b, r); b ^= a;
}
__device__ __forceinline__ void tf2(uint32_t k0, uint32_t k1, uint32_t x0, uint32_t x1,
                                    uint32_t& o0, uint32_t& o1) {
    uint32_t k2 = k0 ^ k1 ^ 0x1BD11BDAu;
    x0 += k0; x1 += k1;
    tfr(x0,x1,13); tfr(x0,x1,15); tfr(x0,x1,26); tfr(x0,x1,6);
    x0 += k1; x1 += k2 + 1u;
    tfr(x0,x1,17); tfr(x0,x1,29); tfr(x0,x1,16); tfr(x0,x1,24);
    x0 += k2; x1 += k0 + 2u;
    tfr(x0,x1,13); tfr(x0,x1,15); tfr(x0,x1,26); tfr(x0,x1,6);
    x0 += k0; x1 += k1 + 3u;
    tfr(x0,x1,17); tfr(x0,x1,29); tfr(x0,x1,16); tfr(x0,x1,24);
    x0 += k1; x1 += k2 + 4u;
    tfr(x0,x1,13); tfr(x0,x1,15); tfr(x0,x1,26); tfr(x0,x1,6);
    o0 = x0 + k2; o1 = x1 + k0 + 5u;
}
__device__ __forceinline__ uint2 tchild(uint2 k, uint32_t i) {
    uint32_t a, b; tf2(k.x, k.y, 0u, i, a, b); return make_uint2(a, b);
}
__device__ __forceinline__ float u01(uint2 k, uint32_t i) {
    uint32_t a, b; tf2(k.x, k.y, 0u, i, a, b);
    return __uint_as_float(((a ^ b) >> 9) | 0x3f800000u) - 1.0f;
}
__device__ __forceinline__ float gumbelf(uint2 k, uint32_t i) {
    float f = u01(k, i);
    float u = fmaxf(TINYF, f + TINYF);
    return -logf(-logf(u));
}
// exponential race variable: e = -log(u), bit-identical to reference's inner -log(u)
__device__ __forceinline__ float expvarf(uint2 k, uint32_t i) {
    float f = u01(k, i);
    float u = fmaxf(TINYF, f + TINYF);
    return -logf(u);
}

// ---------- XLA-matched math (exact; used on argmax-feeding paths) ----------
__device__ __forceinline__ float sigmf(float x) { return 1.0f / (1.0f + expf(-x)); }
__device__ __forceinline__ float softplusf(float x) {
    return fmaxf(x, 0.0f) + log1pf(expf(-fabsf(x)));
}

// ---------- k0: keys + zero counts ----------
__global__ void k_init() {
    int t = threadIdx.x + blockIdx.x * blockDim.x;
    for (int i = t; i < NVV * NRC; i += gridDim.x * blockDim.x) g_cnts[i] = 0;
    if (t == 0) {
        uint2 root = make_uint2(0u, 42u);
        uint2 kc = tchild(root, 0), kf = tchild(root, 1);
        uint2 cA = tchild(kc, 0), cB = tchild(kc, 1);
        g_keys[0] = tchild(cA, 0); g_keys[1] = tchild(cA, 1); g_keys[2] = tchild(cB, 0);
        uint2 fA = tchild(kf, 0), fB = tchild(kf, 1);
        g_keys[3] = tchild(fA, 0); g_keys[4] = tchild(fA, 1); g_keys[5] = tchild(fA, 2);
        g_keys[6] = tchild(fA, 3); g_keys[7] = tchild(fA, 4);
        g_keys[8] = tchild(fB, 0); g_keys[9] = tchild(fB, 1); g_keys[10] = tchild(fB, 2);
    }
}

// ---------- k1: coarse (numerics untouched — feeds both argmaxes) ----------
__global__ void __launch_bounds__(128) k_coarse(
        const float* __restrict__ Rt, const float* __restrict__ W1,
        const float* __restrict__ b1, const float* __restrict__ w2,
        const float* __restrict__ b2v, float* __restrict__ out) {
    int r = blockIdx.x, v = blockIdx.y, t = threadIdx.x;
    __shared__ float st[NPTS_C], sd[NPTS_C], al[256];
    __shared__ float W1s[192], b1s[64], w2s[64], dirs[3], org[3];
    for (int i = t; i < 192; i += 128) W1s[i] = W1[i];
    for (int i = t; i < 64; i += 128) { b1s[i] = b1[i]; w2s[i] = w2[i]; }
    if (t == 0) {
        float ru  = ((float)(r / 8) + u01(g_keys[0], (uint32_t)(v * NRC + r))) / 64.0f;
        float rv  = ((float)(r % 8) + u01(g_keys[1], (uint32_t)(v * NRC + r))) / 8.0f;
        float phi = ru * TWOPI;
        float ct = rv * (1.0f - MINCOS) + MINCOS;
        float snt = sqrtf(fmaxf(1.0f - ct * ct, 0.0f));
        float d0 = snt * cosf(phi), d1 = snt * sinf(phi), d2 = ct;
        const float* Rv = Rt + v * 12;
        for (int i = 0; i < 3; i++) {
            dirs[i] = d0 * Rv[i*4] + d1 * Rv[i*4+1] + d2 * Rv[i*4+2];
            org[i]  = Rv[i*4+3];
        }
    }
    {
        float eta = u01(g_keys[2], (uint32_t)((v * NRC + r) * 128 + t)) * BINSZ;
        float left = BINSZ * (float)t;
        st[2*t] = left; st[2*t+1] = left + eta;
        if (t == 0) st[256] = BINSZ * 128.0f;
    }
    __syncthreads();
    float b2 = b2v[0];
    for (int k = t; k < NPTS_C; k += 128) {
        float s = st[k];
        float px = org[0] + s*dirs[0], py = org[1] + s*dirs[1], pz = org[2] + s*dirs[2];
        float acc = 0.0f;
        #pragma unroll 8
        for (int j = 0; j < HID; j++) {
            float z = fmaf(pz, W1s[128+j], fmaf(py, W1s[64+j], px * W1s[j])) + b1s[j];
            acc = fmaf(softplusf(z), w2s[j], acc);
        }
        sd[k] = acc + b2;
    }
    __syncthreads();
    for (int k = t; k < 256; k += 128) {
        float dl = st[k+1] - st[k];
        float ck = (sd[k+1] - sd[k]) / (dl + 1e-6f);
        float pv = (k > 0) ? (sd[k] - sd[k-1]) / ((st[k] - st[k-1]) + 1e-6f) : 0.0f;
        float c = fminf(fmaxf(fminf(pv, ck), -1000.0f), 0.0f);
        float ds = 0.5f * c * dl;
        float ms = 0.5f * (sd[k] + sd[k+1]);
        float pT = sigmf(64.0f * (ms - ds)), nT = sigmf(64.0f * (ms + ds));
        float mx = 0.5f*((org[0]+st[k]*dirs[0]) + (org[0]+st[k+1]*dirs[0]));
        float my = 0.5f*((org[1]+st[k]*dirs[1]) + (org[1]+st[k+1]*dirs[1]));
        float mz = 0.5f*((org[2]+st[k]*dirs[2]) + (org[2]+st[k+1]*dirs[2]));
        float nrm = sqrtf(mx*mx + my*my + mz*mz);
        float insf = (nrm < 1.0f && mz > 0.0f) ? 1.0f : 0.0f;
        al[k] = (1.0f - nT / (pT + 1e-6f)) * insf;
    }
    __syncthreads();
    if (t == 0) {
        float T = 1.0f, ray = 0.0f;
        float* spd = out + SP_OFF + (size_t)(v * NRC + r) * NB;
        for (int b = 0; b < NB; b++) {
            float w0 = al[2*b] * T;
            float o0 = 1.0f - al[2*b];   T *= o0*o0 + 1e-6f;
            float w1 = al[2*b+1] * T;
            float o1 = 1.0f - al[2*b+1]; T *= o1*o1 + 1e-6f;
            float sp = w0 + w1; spd[b] = sp; ray += sp;
        }
        out[RP_OFF + (size_t)(v * NRC + r)] = ray;
    }
}

// ---------- k2: ray categorical (exact — a flip here costs ~1e-2) ----------
__global__ void __launch_bounds__(128) k_ray_idx(const float* __restrict__ out) {
    int p = blockIdx.x, v = blockIdx.y, t = threadIdx.x;
    const float* rp = out + RP_OFF + (size_t)v * NRC;
    uint2 kg = g_keys[5];
    float best = -3.4e38f; int bi = 1 << 30;
    for (int s = t; s < NRC; s += 128) {
        float val = gumbelf(kg, (uint32_t)((p * NVV + v) * NRC + s)) + logf(rp[s] + 1e-6f);
        if (val > best || (val == best && s < bi)) { best = val; bi = s; }
    }
    __shared__ float bv[128]; __shared__ int bx[128];
    bv[t] = best; bx[t] = bi; __syncthreads();
    for (int s = 64; s > 0; s >>= 1) {
        if (t < s) {
            if (bv[t+s] > bv[t] || (bv[t+s] == bv[t] && bx[t+s] < bx[t])) {
                bv[t] = bv[t+s]; bx[t] = bx[t+s];
            }
        }
        __syncthreads();
    }
    if (t == 0) {
        g_idx[v * NPDF_RAYS + p] = bx[0];
        atomicAdd(&g_cnts[v * NRC + bx[0]], 1);
    }
}

// ---------- k3: fine ray gen ----------
__global__ void __launch_bounds__(NRF) k_fine_rays(const float* __restrict__ Rt) {
    int v = blockIdx.x, r = threadIdx.x;
    int uv; float U1, U2;
    if (r < NRC) {
        uv = r;
        U1 = u01(g_keys[3], (uint32_t)(v * NRC + r));
        U2 = u01(g_keys[4], (uint32_t)(v * NRC + r));
    } else {
        int p = r - NRC;
        uv = g_idx[v * NPDF_RAYS + p];
        U1 = u01(g_keys[6], (uint32_t)(v * NPDF_RAYS + p));
        U2 = u01(g_keys[7], (uint32_t)(v * NPDF_RAYS + p));
    }
    float ru  = ((float)(uv / 8) + U1) / 64.0f;
    float rv  = ((float)(uv % 8) + U2) / 8.0f;
    float phi = ru * TWOPI;
    float ct = rv * (1.0f - MINCOS) + MINCOS;
    float snt = sqrtf(fmaxf(1.0f - ct * ct, 0.0f));
    float d0 = snt * cosf(phi), d1 = snt * sinf(phi), d2 = ct;
    const float* Rv = Rt + v * 12;
    size_t ray = (size_t)v * NRF + r;
    for (int i = 0; i < 3; i++)
        g_dir[ray*3+i] = d0*Rv[i*4] + d1*Rv[i*4+1] + d2*Rv[i*4+2];
    int cnt = g_cnts[v * NRC + uv];
    float sang = 2.0f * 3.14159265358979323846f * (1.0f - MINCOS);
    g_w[ray] = (1.0f / (((float)cnt + 1.0f) * 512.0f)) * ct * sang;
    g_uv[ray] = uv;
}

// ---------- k4: fine step sampling — exponential races (1 logf/draw-bin) ----------
__global__ void __launch_bounds__(128) k_fine_steps(const float* __restrict__ out) {
    int r = blockIdx.x, v = blockIdx.y, t = threadIdx.x;
    int lane = t & 31, wid = t >> 5;
    __shared__ float rinv[NB], base[NPTS_C], ex[NPDF_STEPS], exs[NPDF_STEPS];
    __shared__ int sbidx[NPDF_STEPS];
    int uv = g_uv[(size_t)v * NRF + r];
    rinv[t] = 1.0f / (out[SP_OFF + (size_t)(v * NRC + uv) * NB + t] + 1e-6f);
    {
        float eta = u01(g_keys[8], (uint32_t)((v * NRF + r) * 128 + t)) * BINSZ;
        float left = BINSZ * (float)t;
        base[2*t] = left; base[2*t+1] = left + eta;
        if (t == 0) base[256] = BINSZ * 128.0f;
    }
    __syncthreads();
    uint2 kg = g_keys[9];
    uint32_t ibase = (uint32_t)((uint32_t)v * NRF + (uint32_t)r) * 128u;
    // 4 warps x 8 draws; argmin of e*(1/w) == argmax of gumbel+logit (races)
    for (int p = wid; p < NPDF_STEPS; p += 4) {
        uint32_t doff = (uint32_t)p * (uint32_t)(NVV * NRF) * 128u + ibase;
        float best = 3.4e38f; int bi = 1 << 30;
        #pragma unroll
        for (int q = 0; q < 4; q++) {
            int bin = lane + q * 32;
            float val = expvarf(kg, doff + (uint32_t)bin) * rinv[bin];
            if (val < best || (val == best && bin < bi)) { best = val; bi = bin; }
        }
        #pragma unroll
        for (int o = 16; o > 0; o >>= 1) {
            float v2 = __shfl_down_sync(0xffffffffu, best, o);
            int   i2 = __shfl_down_sync(0xffffffffu, bi, o);
            if (v2 < best || (v2 == best && i2 < bi)) { best = v2; bi = i2; }
        }
        if (lane == 0) sbidx[p] = bi;
    }
    __syncthreads();
    if (t < NPDF_STEPS)
        ex[t] = BINSZ * (float)sbidx[t] + u01(g_keys[10], (uint32_t)((v * NRF + r) * 32 + t)) * BINSZ;
    __syncthreads();
    if (t < NPDF_STEPS) {   // parallel rank sort of 32 extras
        float x = ex[t]; int rank = 0;
        #pragma unroll
        for (int j = 0; j < NPDF_STEPS; j++) {
            float y = ex[j];
            rank += (y < x) || (y == x && j < t);
        }
        exs[rank] = x;
    }
    __syncthreads();
    float* dst = g_steps + ((size_t)v * NRF + r) * NPTS_F;
    for (int k = t; k < NPTS_C; k += 128) {
        float x = base[k]; int lo = 0, hi = NPDF_STEPS;
        while (lo < hi) { int m = (lo+hi)>>1; if (exs[m] < x) lo = m+1; else hi = m; }
        dst[k + lo] = x;
    }
    if (t < NPDF_STEPS) {
        float x = exs[t]; int lo = 0, hi = NPTS_C;
        while (lo < hi) { int m = (lo+hi)>>1; if (base[m] <= x) lo = m+1; else hi = m; }
        dst[t + lo] = x;
    }
}

// ---------- k5: fine main — fast transcendentals + parallel scan/scatter ----------
__global__ void __launch_bounds__(96) k_fine_main(
        const float* __restrict__ Rt, const float* __restrict__ W1,
        const float* __restrict__ b1, const float* __restrict__ w2,
        const float* __restrict__ b2v, const float* __restrict__ inv_sv,
        const float* __restrict__ rhov, float* __restrict__ out) {
    int r = blockIdx.x, v = blockIdx.y, t = threadIdx.x;
    int lane = t & 31, wid = t >> 5;
    __shared__ float W1s[192], b1s[64], w2s[64];
    __shared__ float al[NPF], rf[NPF], Ts[NPF];
    __shared__ int bidxs[NPF];
    __shared__ unsigned char vfl[NPF];
    __shared__ float wtot[3];
    __shared__ float bwv[NB];
    for (int i = t; i < 192; i += 96) W1s[i] = W1[i];
    for (int i = t; i < 64; i += 96) { b1s[i] = b1[i]; w2s[i] = w2[i]; }
    size_t ray = (size_t)v * NRF + r;
    const float* se = g_steps + ray * NPTS_F;
    float dx = g_dir[ray*3], dy = g_dir[ray*3+1], dz = g_dir[ray*3+2];
    const float* Rv = Rt + v * 12;
    float ox = Rv[3], oy = Rv[7], oz = Rv[11];
    float b2 = b2v[0], inv_s = inv_sv[0], rho = rhov[0];
    __syncthreads();
    for (int k = t; k < NPF; k += 96) {
        float s0 = se[k], s1 = se[k+1];
        float delta = s1 - s0, sm = 0.5f * (s1 + s0);
        float px = ox + sm*dx, py = oy + sm*dy, pz = oz + sm*dz;
        float nrm = sqrtf(px*px + py*py + pz*pz);
        float insf = (nrm < 1.0f && pz > 0.0f) ? 1.0f : 0.0f;
        float sdf = 0.0f, n0 = 0.0f, n1 = 0.0f, n2 = 0.0f;
        #pragma unroll 8
        for (int j = 0; j < HID; j++) {
            float w0j = W1s[j], w1j = W1s[64+j], w2j = W1s[128+j];
            float z = fmaf(pz, w2j, fmaf(py, w1j, px * w0j)) + b1s[j];
            float tE = __expf(-fabsf(z));
            sdf = fmaf(fmaxf(z, 0.0f) + __logf(1.0f + tE), w2s[j], sdf);
            float inv = __fdividef(1.0f, 1.0f + tE);
            float sg = ((z >= 0.0f) ? inv : tE * inv) * w2s[j];
            n0 = fmaf(sg, w0j, n0); n1 = fmaf(sg, w1j, n1); n2 = fmaf(sg, w2j, n2);
        }
        sdf = (sdf + b2) * insf; n0 *= insf; n1 *= insf; n2 *= insf;
        out[SDF_OFF + ray*NPF + k] = sdf;
        out[NORM_OFF + (ray*NPF + k)*3 + 0] = n0;
        out[NORM_OFF + (ray*NPF + k)*3 + 1] = n1;
        out[NORM_OFF + (ray*NPF + k)*3 + 2] = n2;
        float cs = dx*n0 + dy*n1 + dz*n2;
        float ac = -fmaxf(fmaf(cs, -0.5f, 0.5f), 0.0f);
        float ds = 0.5f * ac * delta;
        float argp = inv_s * (sdf - ds), argn = inv_s * (sdf + ds);
        float pT = __fdividef(1.0f, 1.0f + __expf(-argp));
        float nT = __fdividef(1.0f, 1.0f + __expf(-argn));
        float a = (1.0f - nT / (pT + 1e-6f)) * insf;
        out[ALPHA_OFF + ray*NPF + k] = a;
        al[k] = a;
        rf[k] = rho * (-ac * __fdividef(1.0f, sm*sm + 1e-6f));
        int bi = (int)floorf(sm / BINSZ);            // exact division (bin identity)
        bi = max(0, min(NB - 1, bi));
        bool valid = (sm > (float)bi * BINSZ) && (sm < (float)(bi+1) * BINSZ);
        bidxs[k] = bi;                                // non-decreasing (steps sorted)
        vfl[k] = valid ? 1 : 0;
    }
    __syncthreads();
    // parallel prefix product: thread t owns k = 3t, 3t+1, 3t+2
    {
        float a0 = al[3*t], a1 = al[3*t+1], a2 = al[3*t+2];
        float q0 = (1.0f - a0) * (1.0f - a0);
        float q1 = (1.0f - a1) * (1.0f - a1);
        float q2 = (1.0f - a2) * (1.0f - a2);
        float loc = q0 * q1 * q2;
        float inc = loc;
        #pragma unroll
        for (int o = 1; o < 32; o <<= 1) {
            float u = __shfl_up_sync(0xffffffffu, inc, o);
            if (lane >= o) inc *= u;
        }
        float exc = __shfl_up_sync(0xffffffffu, inc, 1);
        if (lane == 0) exc = 1.0f;
        if (lane == 31) wtot[wid] = inc;
        __syncthreads();
        float off = 1.0f;
        if (wid >= 1) off *= wtot[0];
        if (wid >= 2) off *= wtot[1];
        float P = off * exc;
        Ts[3*t]   = P;
        Ts[3*t+1] = P * q0;
        Ts[3*t+2] = P * q0 * q1;
    }
    __syncthreads();
    for (int k = t; k < NPF; k += 96) {
        out[T_OFF + ray*NPF + k] = Ts[k];
        out[W_OFF + ray*NPF + k] = al[k] * Ts[k];
    }
    // deterministic per-bin scatter: bin ranges are contiguous in k
    for (int b = t; b < NB; b += 96) {
        int lo = 0, hi = NPF;
        while (lo < hi) { int m = (lo+hi)>>1; if (bidxs[m] < b) lo = m+1; else hi = m; }
        float ba = 0.0f, bw = 0.0f, br = 0.0f;
        for (int k = lo; k < NPF && bidxs[k] == b; k++) {
            if (vfl[k]) {
                float wk = al[k] * Ts[k];
                ba += al[k]; bw += wk; br += wk * rf[k];
            }
        }
        out[BA_OFF + ray*NB + b] = ba;
        out[BW_OFF + ray*NB + b] = bw;
        g_radbins[ray*NB + b] = br;
        bwv[b] = bw;
    }
    __syncthreads();
    if (wid == 0) {   // opacity = sum over bins (matches reference structure)
        float s = bwv[lane] + bwv[lane+32] + bwv[lane+64] + bwv[lane+96];
        #pragma unroll
        for (int o = 16; o > 0; o >>= 1) s += __shfl_down_sync(0xffffffffu, s, o);
        if (lane == 0) out[OP_OFF + ray] = s;
    }
}

// ---------- k6: hists ----------
__global__ void __launch_bounds__(NB) k_hists(float* __restrict__ out) {
    int v = blockIdx.x, b = threadIdx.x;
    float acc = 0.0f;
    for (int r = 0; r < NRF; r++)
        acc += g_radbins[((size_t)v * NRF + r) * NB + b] * g_w[v * NRF + r];
    out[HIST_OFF + (size_t)v * NB + b] = acc;
}

extern "C" void kernel_launch(void* const* d_in, const int* in_sizes, int n_in,
                              void* d_out, int out_size) {
    const float* Rt = (const float*)d_in[0];
    const float* W1 = (const float*)d_in[1];
    const float* b1 = (const float*)d_in[2];
    const float* w2 = (const float*)d_in[3];
    const float* b2 = (const float*)d_in[4];
    const float* inv_s = (const float*)d_in[5];
    const float* rho = (const float*)d_in[6];
    float* out = (float*)d_out;
    k_init<<<64, 256>>>();
    k_coarse<<<dim3(NRC, NVV), 128>>>(Rt, W1, b1, w2, b2, out);
    k_ray_idx<<<dim3(NPDF_RAYS, NVV), 128>>>(out);
    k_fine_rays<<<NVV, NRF>>>(Rt);
    k_fine_steps<<<dim3(NRF, NVV), 128>>>(out);
    k_fine_main<<<dim3(NRF, NVV), 96>>>(Rt, W1, b1, w2, b2, inv_s, rho, out);
    k_hists<<<NVV, NB>>>(out);
}

// round 16
// speedup vs baseline: 1.7386x; 1.0066x over previous
#include <cuda_runtime.h>
#include <stdint.h>

#define NVV 32
#define NRC 512
#define NRF 576
#define NPDF_RAYS 64
#define NB 128
#define NPTS_C 257
#define NPTS_F 289
#define NPF 288
#define NPDF_STEPS 32
#define HID 64
#define BINSZ 0.015f
#define TWOPI 6.283185307179586f
#define MINCOS 0.8660254037844386468f
#define TINYF 1.17549435e-38f
#define NRAYC (NVV * NRC)

#define HIST_OFF  ((size_t)0)
#define SDF_OFF   ((size_t)4096)
#define NORM_OFF  ((size_t)5312512)
#define ALPHA_OFF ((size_t)21237760)
#define T_OFF     ((size_t)26546176)
#define W_OFF     ((size_t)31854592)
#define BA_OFF    ((size_t)37163008)
#define BW_OFF    ((size_t)39522304)
#define OP_OFF    ((size_t)41881600)
#define RP_OFF    ((size_t)41900032)
#define SP_OFF    ((size_t)41916416)

__device__ uint2 g_keys[12];
__device__ int   g_cnts[NRAYC];
__device__ int   g_idx[NVV * NPDF_RAYS];
__device__ float g_dir[NVV * NRF * 3];
__device__ float g_w[NVV * NRF];
__device__ int   g_uv[NVV * NRF];
__device__ float g_steps[(size_t)NVV * NRF * NPTS_F];
__device__ float g_radbins[(size_t)NVV * NRF * NB];
__device__ float g_al[(size_t)256 * NRAYC];   // coarse alphas, [k][ray] layout

// ---------- threefry2x32 ----------
__device__ __forceinline__ void tfr(uint32_t& a, uint32_t& b, int r) {
    a += b; b = __funnelshift_l(b, b, r); b ^= a;
}
__device__ __forceinline__ void tf2(uint32_t k0, uint32_t k1, uint32_t x0, uint32_t x1,
                                    uint32_t& o0, uint32_t& o1) {
    uint32_t k2 = k0 ^ k1 ^ 0x1BD11BDAu;
    x0 += k0; x1 += k1;
    tfr(x0,x1,13); tfr(x0,x1,15); tfr(x0,x1,26); tfr(x0,x1,6);
    x0 += k1; x1 += k2 + 1u;
    tfr(x0,x1,17); tfr(x0,x1,29); tfr(x0,x1,16); tfr(x0,x1,24);
    x0 += k2; x1 += k0 + 2u;
    tfr(x0,x1,13); tfr(x0,x1,15); tfr(x0,x1,26); tfr(x0,x1,6);
    x0 += k0; x1 += k1 + 3u;
    tfr(x0,x1,17); tfr(x0,x1,29); tfr(x0,x1,16); tfr(x0,x1,24);
    x0 += k1; x1 += k2 + 4u;
    tfr(x0,x1,13); tfr(x0,x1,15); tfr(x0,x1,26); tfr(x0,x1,6);
    o0 = x0 + k2; o1 = x1 + k0 + 5u;
}
__device__ __forceinline__ uint2 tchild(uint2 k, uint32_t i) {
    uint32_t a, b; tf2(k.x, k.y, 0u, i, a, b); return make_uint2(a, b);
}
__device__ __forceinline__ float u01(uint2 k, uint32_t i) {
    uint32_t a, b; tf2(k.x, k.y, 0u, i, a, b);
    return __uint_as_float(((a ^ b) >> 9) | 0x3f800000u) - 1.0f;
}
__device__ __forceinline__ float gumbelf(uint2 k, uint32_t i) {   // exact (ray argmax)
    float f = u01(k, i);
    float u = fmaxf(TINYF, f + TINYF);
    return -logf(-logf(u));
}
// exponential race variable — EXACT logf is mandatory: race winners have u≈1,
// where __logf's absolute error ~1e-7 is ~100% relative error on the result.
__device__ __forceinline__ float expvarf(uint2 k, uint32_t i) {
    float f = u01(k, i);
    float u = fmaxf(TINYF, f + TINYF);
    return -logf(u);
}

// ---------- math ----------
__device__ __forceinline__ float sigmf(float x) { return 1.0f / (1.0f + expf(-x)); }
__device__ __forceinline__ float softplusf(float x) {             // exact form (coarse)
    return fmaxf(x, 0.0f) + log1pf(expf(-fabsf(x)));
}

// ---------- k0: keys + zero counts ----------
__global__ void k_init() {
    int t = threadIdx.x + blockIdx.x * blockDim.x;
    for (int i = t; i < NRAYC; i += gridDim.x * blockDim.x) g_cnts[i] = 0;
    if (t == 0) {
        uint2 root = make_uint2(0u, 42u);
        uint2 kc = tchild(root, 0), kf = tchild(root, 1);
        uint2 cA = tchild(kc, 0), cB = tchild(kc, 1);
        g_keys[0] = tchild(cA, 0); g_keys[1] = tchild(cA, 1); g_keys[2] = tchild(cB, 0);
        uint2 fA = tchild(kf, 0), fB = tchild(kf, 1);
        g_keys[3] = tchild(fA, 0); g_keys[4] = tchild(fA, 1); g_keys[5] = tchild(fA, 2);
        g_keys[6] = tchild(fA, 3); g_keys[7] = tchild(fA, 4);
        g_keys[8] = tchild(fB, 0); g_keys[9] = tchild(fB, 1); g_keys[10] = tchild(fB, 2);
    }
}

// ---------- k1: coarse (EXACT numerics; serial tail moved out) ----------
__global__ void __launch_bounds__(128) k_coarse(
        const float* __restrict__ Rt, const float* __restrict__ W1,
        const float* __restrict__ b1, const float* __restrict__ w2,
        const float* __restrict__ b2v) {
    int r = blockIdx.x, v = blockIdx.y, t = threadIdx.x;
    int rayid = v * NRC + r;
    __shared__ float st[NPTS_C], sd[NPTS_C];
    __shared__ float W1s[192], b1s[64], w2s[64], dirs[3], org[3];
    for (int i = t; i < 192; i += 128) W1s[i] = W1[i];
    for (int i = t; i < 64; i += 128) { b1s[i] = b1[i]; w2s[i] = w2[i]; }
    if (t == 0) {
        float ru  = ((float)(r / 8) + u01(g_keys[0], (uint32_t)rayid)) / 64.0f;
        float rv  = ((float)(r % 8) + u01(g_keys[1], (uint32_t)rayid)) / 8.0f;
        float phi = ru * TWOPI;
        float ct = rv * (1.0f - MINCOS) + MINCOS;
        float snt = sqrtf(fmaxf(1.0f - ct * ct, 0.0f));
        float d0 = snt * cosf(phi), d1 = snt * sinf(phi), d2 = ct;
        const float* Rv = Rt + v * 12;
        for (int i = 0; i < 3; i++) {
            dirs[i] = d0 * Rv[i*4] + d1 * Rv[i*4+1] + d2 * Rv[i*4+2];
            org[i]  = Rv[i*4+3];
        }
    }
    {
        float eta = u01(g_keys[2], (uint32_t)(rayid * 128 + t)) * BINSZ;
        float left = BINSZ * (float)t;
        st[2*t] = left; st[2*t+1] = left + eta;
        if (t == 0) st[256] = BINSZ * 128.0f;
    }
    __syncthreads();
    float b2 = b2v[0];
    for (int k = t; k < NPTS_C; k += 128) {
        float s = st[k];
        float px = org[0] + s*dirs[0], py = org[1] + s*dirs[1], pz = org[2] + s*dirs[2];
        float acc = 0.0f;
        #pragma unroll 8
        for (int j = 0; j < HID; j++) {
            float z = fmaf(pz, W1s[128+j], fmaf(py, W1s[64+j], px * W1s[j])) + b1s[j];
            acc = fmaf(softplusf(z), w2s[j], acc);
        }
        sd[k] = acc + b2;
    }
    __syncthreads();
    for (int k = t; k < 256; k += 128) {
        float dl = st[k+1] - st[k];
        float ck = (sd[k+1] - sd[k]) / (dl + 1e-6f);
        float pv = (k > 0) ? (sd[k] - sd[k-1]) / ((st[k] - st[k-1]) + 1e-6f) : 0.0f;
        float c = fminf(fmaxf(fminf(pv, ck), -1000.0f), 0.0f);
        float ds = 0.5f * c * dl;
        float ms = 0.5f * (sd[k] + sd[k+1]);
        float pT = sigmf(64.0f * (ms - ds)), nT = sigmf(64.0f * (ms + ds));
        float mx = 0.5f*((org[0]+st[k]*dirs[0]) + (org[0]+st[k+1]*dirs[0]));
        float my = 0.5f*((org[1]+st[k]*dirs[1]) + (org[1]+st[k+1]*dirs[1]));
        float mz = 0.5f*((org[2]+st[k]*dirs[2]) + (org[2]+st[k+1]*dirs[2]));
        float nrm = sqrtf(mx*mx + my*my + mz*mz);
        float insf = (nrm < 1.0f && mz > 0.0f) ? 1.0f : 0.0f;
        g_al[(size_t)k * NRAYC + rayid] = (1.0f - nT / (pT + 1e-6f)) * insf;
    }
}

// ---------- k1b: coarse tail — 1 thread/ray, bit-exact sequential order ----------
__global__ void __launch_bounds__(128) k_coarse_tail(float* __restrict__ out) {
    int ray = blockIdx.x * blockDim.x + threadIdx.x;
    if (ray >= NRAYC) return;
    float T = 1.0f, rsum = 0.0f;
    float* spd = out + SP_OFF + (size_t)ray * NB;
    for (int b = 0; b < NB; b++) {
        float a0 = g_al[(size_t)(2*b)   * NRAYC + ray];
        float a1 = g_al[(size_t)(2*b+1) * NRAYC + ray];
        float w0 = a0 * T;
        float o0 = 1.0f - a0;   T *= o0*o0 + 1e-6f;
        float w1 = a1 * T;
        float o1 = 1.0f - a1;   T *= o1*o1 + 1e-6f;
        float sp = w0 + w1; spd[b] = sp; rsum += sp;
    }
    out[RP_OFF + (size_t)ray] = rsum;
}

// ---------- k2: ray categorical (exact) ----------
__global__ void __launch_bounds__(128) k_ray_idx(const float* __restrict__ out) {
    int p = blockIdx.x, v = blockIdx.y, t = threadIdx.x;
    const float* rp = out + RP_OFF + (size_t)v * NRC;
    uint2 kg = g_keys[5];
    float best = -3.4e38f; int bi = 1 << 30;
    for (int s = t; s < NRC; s += 128) {
        float val = gumbelf(kg, (uint32_t)((p * NVV + v) * NRC + s)) + logf(rp[s] + 1e-6f);
        if (val > best || (val == best && s < bi)) { best = val; bi = s; }
    }
    __shared__ float bv[128]; __shared__ int bx[128];
    bv[t] = best; bx[t] = bi; __syncthreads();
    for (int s = 64; s > 0; s >>= 1) {
        if (t < s) {
            if (bv[t+s] > bv[t] || (bv[t+s] == bv[t] && bx[t+s] < bx[t])) {
                bv[t] = bv[t+s]; bx[t] = bx[t+s];
            }
        }
        __syncthreads();
    }
    if (t == 0) {
        g_idx[v * NPDF_RAYS + p] = bx[0];
        atomicAdd(&g_cnts[v * NRC + bx[0]], 1);
    }
}

// ---------- k3: fine ray gen ----------
__global__ void __launch_bounds__(NRF) k_fine_rays(const float* __restrict__ Rt) {
    int v = blockIdx.x, r = threadIdx.x;
    int uv; float U1, U2;
    if (r < NRC) {
        uv = r;
        U1 = u01(g_keys[3], (uint32_t)(v * NRC + r));
        U2 = u01(g_keys[4], (uint32_t)(v * NRC + r));
    } else {
        int p = r - NRC;
        uv = g_idx[v * NPDF_RAYS + p];
        U1 = u01(g_keys[6], (uint32_t)(v * NPDF_RAYS + p));
        U2 = u01(g_keys[7], (uint32_t)(v * NPDF_RAYS + p));
    }
    float ru  = ((float)(uv / 8) + U1) / 64.0f;
    float rv  = ((float)(uv % 8) + U2) / 8.0f;
    float phi = ru * TWOPI;
    float ct = rv * (1.0f - MINCOS) + MINCOS;
    float snt = sqrtf(fmaxf(1.0f - ct * ct, 0.0f));
    float d0 = snt * cosf(phi), d1 = snt * sinf(phi), d2 = ct;
    const float* Rv = Rt + v * 12;
    size_t ray = (size_t)v * NRF + r;
    for (int i = 0; i < 3; i++)
        g_dir[ray*3+i] = d0*Rv[i*4] + d1*Rv[i*4+1] + d2*Rv[i*4+2];
    int cnt = g_cnts[v * NRC + uv];
    float sang = 2.0f * 3.14159265358979323846f * (1.0f - MINCOS);
    g_w[ray] = (1.0f / (((float)cnt + 1.0f) * 512.0f)) * ct * sang;
    g_uv[ray] = uv;
}

// ---------- k4: fine step sampling — exact race numerics (round-10 bits) ----------
__global__ void __launch_bounds__(128) k_fine_steps(const float* __restrict__ out) {
    int r = blockIdx.x, v = blockIdx.y, t = threadIdx.x;
    int lane = t & 31, wid = t >> 5;
    __shared__ float rinv[NB], base[NPTS_C], ex[NPDF_STEPS], exs[NPDF_STEPS];
    __shared__ int sbidx[NPDF_STEPS];
    int uv = g_uv[(size_t)v * NRF + r];
    rinv[t] = 1.0f / (out[SP_OFF + (size_t)(v * NRC + uv) * NB + t] + 1e-6f);
    {
        float eta = u01(g_keys[8], (uint32_t)((v * NRF + r) * 128 + t)) * BINSZ;
        float left = BINSZ * (float)t;
        base[2*t] = left; base[2*t+1] = left + eta;
        if (t == 0) base[256] = BINSZ * 128.0f;
    }
    __syncthreads();
    uint2 kg = g_keys[9];
    uint32_t ibase = (uint32_t)((uint32_t)v * NRF + (uint32_t)r) * 128u;
    for (int p = wid; p < NPDF_STEPS; p += 4) {
        uint32_t doff = (uint32_t)p * (uint32_t)(NVV * NRF) * 128u + ibase;
        float best = 3.4e38f; int bi = 1 << 30;
        #pragma unroll
        for (int q = 0; q < 4; q++) {
            int bin = lane + q * 32;
            float val = expvarf(kg, doff + (uint32_t)bin) * rinv[bin];
            if (val < best || (val == best && bin < bi)) { best = val; bi = bin; }
        }
        #pragma unroll
        for (int o = 16; o > 0; o >>= 1) {
            float v2 = __shfl_down_sync(0xffffffffu, best, o);
            int   i2 = __shfl_down_sync(0xffffffffu, bi, o);
            if (v2 < best || (v2 == best && i2 < bi)) { best = v2; bi = i2; }
        }
        if (lane == 0) sbidx[p] = bi;
    }
    __syncthreads();
    if (t < NPDF_STEPS)
        ex[t] = BINSZ * (float)sbidx[t] + u01(g_keys[10], (uint32_t)((v * NRF + r) * 32 + t)) * BINSZ;
    __syncthreads();
    if (t < NPDF_STEPS) {
        float x = ex[t]; int rank = 0;
        #pragma unroll
        for (int j = 0; j < NPDF_STEPS; j++) {
            float y = ex[j];
            rank += (y < x) || (y == x && j < t);
        }
        exs[rank] = x;
    }
    __syncthreads();
    float* dst = g_steps + ((size_t)v * NRF + r) * NPTS_F;
    for (int k = t; k < NPTS_C; k += 128) {
        float x = base[k]; int lo = 0, hi = NPDF_STEPS;
        while (lo < hi) { int m = (lo+hi)>>1; if (exs[m] < x) lo = m+1; else hi = m; }
        dst[k + lo] = x;
    }
    if (t < NPDF_STEPS) {
        float x = exs[t]; int lo = 0, hi = NPTS_C;
        while (lo < hi) { int m = (lo+hi)>>1; if (base[m] <= x) lo = m+1; else hi = m; }
        dst[t + lo] = x;
    }
}

// ---------- k5: fine main — fast transcendentals + parallel scan/scatter ----------
__global__ void __launch_bounds__(96) k_fine_main(
        const float* __restrict__ Rt, const float* __restrict__ W1,
        const float* __restrict__ b1, const float* __restrict__ w2,
        const float* __restrict__ b2v, const float* __restrict__ inv_sv,
        const float* __restrict__ rhov, float* __restrict__ out) {
    int r = blockIdx.x, v = blockIdx.y, t = threadIdx.x;
    int lane = t & 31, wid = t >> 5;
    __shared__ float W1s[192], b1s[64], w2s[64];
    __shared__ float al[NPF], rf[NPF], Ts[NPF];
    __shared__ int bidxs[NPF];
    __shared__ unsigned char vfl[NPF];
    __shared__ float wtot[3];
    __shared__ float bwv[NB];
    for (int i = t; i < 192; i += 96) W1s[i] = W1[i];
    for (int i = t; i < 64; i += 96) { b1s[i] = b1[i]; w2s[i] = w2[i]; }
    size_t ray = (size_t)v * NRF + r;
    const float* se = g_steps + ray * NPTS_F;
    float dx = g_dir[ray*3], dy = g_dir[ray*3+1], dz = g_dir[ray*3+2];
    const float* Rv = Rt + v * 12;
    float ox = Rv[3], oy = Rv[7], oz = Rv[11];
    float b2 = b2v[0], inv_s = inv_sv[0], rho = rhov[0];
    __syncthreads();
    for (int k = t; k < NPF; k += 96) {
        float s0 = se[k], s1 = se[k+1];
        float delta = s1 - s0, sm = 0.5f * (s1 + s0);
        float px = ox + sm*dx, py = oy + sm*dy, pz = oz + sm*dz;
        float nrm = sqrtf(px*px + py*py + pz*pz);
        float insf = (nrm < 1.0f && pz > 0.0f) ? 1.0f : 0.0f;
        float sdf = 0.0f, n0 = 0.0f, n1 = 0.0f, n2 = 0.0f;
        #pragma unroll 8
        for (int j = 0; j < HID; j++) {
            float w0j = W1s[j], w1j = W1s[64+j], w2j = W1s[128+j];
            float z = fmaf(pz, w2j, fmaf(py, w1j, px * w0j)) + b1s[j];
            float tE = __expf(-fabsf(z));
            sdf = fmaf(fmaxf(z, 0.0f) + __logf(1.0f + tE), w2s[j], sdf);
            float inv = __fdividef(1.0f, 1.0f + tE);
            float sg = ((z >= 0.0f) ? inv : tE * inv) * w2s[j];
            n0 = fmaf(sg, w0j, n0); n1 = fmaf(sg, w1j, n1); n2 = fmaf(sg, w2j, n2);
        }
        sdf = (sdf + b2) * insf; n0 *= insf; n1 *= insf; n2 *= insf;
        out[SDF_OFF + ray*NPF + k] = sdf;
        out[NORM_OFF + (ray*NPF + k)*3 + 0] = n0;
        out[NORM_OFF + (ray*NPF + k)*3 + 1] = n1;
        out[NORM_OFF + (ray*NPF + k)*3 + 2] = n2;
        float cs = dx*n0 + dy*n1 + dz*n2;
        float ac = -fmaxf(fmaf(cs, -0.5f, 0.5f), 0.0f);
        float ds = 0.5f * ac * delta;
        float argp = inv_s * (sdf - ds), argn = inv_s * (sdf + ds);
        float pT = __fdividef(1.0f, 1.0f + __expf(-argp));
        float nT = __fdividef(1.0f, 1.0f + __expf(-argn));
        float a = (1.0f - nT / (pT + 1e-6f)) * insf;
        out[ALPHA_OFF + ray*NPF + k] = a;
        al[k] = a;
        rf[k] = rho * (-ac * __fdividef(1.0f, sm*sm + 1e-6f));
        int bi = (int)floorf(sm / BINSZ);
        bi = max(0, min(NB - 1, bi));
        bool valid = (sm > (float)bi * BINSZ) && (sm < (float)(bi+1) * BINSZ);
        bidxs[k] = bi;
        vfl[k] = valid ? 1 : 0;
    }
    __syncthreads();
    {
        float a0 = al[3*t], a1 = al[3*t+1], a2 = al[3*t+2];
        float q0 = (1.0f - a0) * (1.0f - a0);
        float q1 = (1.0f - a1) * (1.0f - a1);
        float q2 = (1.0f - a2) * (1.0f - a2);
        float loc = q0 * q1 * q2;
        float inc = loc;
        #pragma unroll
        for (int o = 1; o < 32; o <<= 1) {
            float u = __shfl_up_sync(0xffffffffu, inc, o);
            if (lane >= o) inc *= u;
        }
        float exc = __shfl_up_sync(0xffffffffu, inc, 1);
        if (lane == 0) exc = 1.0f;
        if (lane == 31) wtot[wid] = inc;
        __syncthreads();
        float off = 1.0f;
        if (wid >= 1) off *= wtot[0];
        if (wid >= 2) off *= wtot[1];
        float P = off * exc;
        Ts[3*t]   = P;
        Ts[3*t+1] = P * q0;
        Ts[3*t+2] = P * q0 * q1;
    }
    __syncthreads();
    for (int k = t; k < NPF; k += 96) {
        out[T_OFF + ray*NPF + k] = Ts[k];
        out[W_OFF + ray*NPF + k] = al[k] * Ts[k];
    }
    for (int b = t; b < NB; b += 96) {
        int lo = 0, hi = NPF;
        while (lo < hi) { int m = (lo+hi)>>1; if (bidxs[m] < b) lo = m+1; else hi = m; }
        float ba = 0.0f, bw = 0.0f, br = 0.0f;
        for (int k = lo; k < NPF && bidxs[k] == b; k++) {
            if (vfl[k]) {
                float wk = al[k] * Ts[k];
                ba += al[k]; bw += wk; br += wk * rf[k];
            }
        }
        out[BA_OFF + ray*NB + b] = ba;
        out[BW_OFF + ray*NB + b] = bw;
        g_radbins[ray*NB + b] = br;
        bwv[b] = bw;
    }
    __syncthreads();
    if (wid == 0) {
        float s = bwv[lane] + bwv[lane+32] + bwv[lane+64] + bwv[lane+96];
        #pragma unroll
        for (int o = 16; o > 0; o >>= 1) s += __shfl_down_sync(0xffffffffu, s, o);
        if (lane == 0) out[OP_OFF + ray] = s;
    }
}

// ---------- k6: hists ----------
__global__ void __launch_bounds__(NB) k_hists(float* __restrict__ out) {
    int v = blockIdx.x, b = threadIdx.x;
    float acc = 0.0f;
    for (int r = 0; r < NRF; r++)
        acc += g_radbins[((size_t)v * NRF + r) * NB + b] * g_w[v * NRF + r];
    out[HIST_OFF + (size_t)v * NB + b] = acc;
}

extern "C" void kernel_launch(void* const* d_in, const int* in_sizes, int n_in,
                              void* d_out, int out_size) {
    const float* Rt = (const float*)d_in[0];
    const float* W1 = (const float*)d_in[1];
    const float* b1 = (const float*)d_in[2];
    const float* w2 = (const float*)d_in[3];
    const float* b2 = (const float*)d_in[4];
    const float* inv_s = (const float*)d_in[5];
    const float* rho = (const float*)d_in[6];
    float* out = (float*)d_out;
    k_init<<<64, 256>>>();
    k_coarse<<<dim3(NRC, NVV), 128>>>(Rt, W1, b1, w2, b2);
    k_coarse_tail<<<NRAYC / 128, 128>>>(out);
    k_ray_idx<<<dim3(NPDF_RAYS, NVV), 128>>>(out);
    k_fine_rays<<<NVV, NRF>>>(Rt);
    k_fine_steps<<<dim3(NRF, NVV), 128>>>(out);
    k_fine_main<<<dim3(NRF, NVV), 96>>>(Rt, W1, b1, w2, b2, inv_s, rho, out);
    k_hists<<<NVV, NB>>>(out);
}

// round 17
// speedup vs baseline: 2.2083x; 1.2702x over previous
#include <cuda_runtime.h>
#include <stdint.h>

#define NVV 32
#define NRC 512
#define NRF 576
#define NPDF_RAYS 64
#define NB 128
#define NPTS_C 257
#define NPTS_F 289
#define NPF 288
#define NPDF_STEPS 32
#define HID 64
#define BINSZ 0.015f
#define TWOPI 6.283185307179586f
#define MINCOS 0.8660254037844386468f
#define TINYF 1.17549435e-38f
#define NRAYC (NVV * NRC)

#define HIST_OFF  ((size_t)0)
#define SDF_OFF   ((size_t)4096)
#define NORM_OFF  ((size_t)5312512)
#define ALPHA_OFF ((size_t)21237760)
#define T_OFF     ((size_t)26546176)
#define W_OFF     ((size_t)31854592)
#define BA_OFF    ((size_t)37163008)
#define BW_OFF    ((size_t)39522304)
#define OP_OFF    ((size_t)41881600)
#define RP_OFF    ((size_t)41900032)
#define SP_OFF    ((size_t)41916416)

__device__ uint2 g_keys[12];
__device__ int   g_cnts[NRAYC];
__device__ int   g_idx[NVV * NPDF_RAYS];
__device__ float g_dir[NVV * NRF * 3];
__device__ float g_w[NVV * NRF];
__device__ int   g_uv[NVV * NRF];
__device__ float g_steps[(size_t)NVV * NRF * NPTS_F];
__device__ float g_radbins[(size_t)NVV * NRF * NB];
__device__ float g_al[(size_t)256 * NRAYC];   // coarse alphas, [k][ray] layout

// ---------- threefry2x32 ----------
__device__ __forceinline__ void tfr(uint32_t& a, uint32_t& b, int r) {
    a += b; b = __funnelshift_l(b, b, r); b ^= a;
}
__device__ __forceinline__ void tf2(uint32_t k0, uint32_t k1, uint32_t x0, uint32_t x1,
                                    uint32_t& o0, uint32_t& o1) {
    uint32_t k2 = k0 ^ k1 ^ 0x1BD11BDAu;
    x0 += k0; x1 += k1;
    tfr(x0,x1,13); tfr(x0,x1,15); tfr(x0,x1,26); tfr(x0,x1,6);
    x0 += k1; x1 += k2 + 1u;
    tfr(x0,x1,17); tfr(x0,x1,29); tfr(x0,x1,16); tfr(x0,x1,24);
    x0 += k2; x1 += k0 + 2u;
    tfr(x0,x1,13); tfr(x0,x1,15); tfr(x0,x1,26); tfr(x0,x1,6);
    x0 += k0; x1 += k1 + 3u;
    tfr(x0,x1,17); tfr(x0,x1,29); tfr(x0,x1,16); tfr(x0,x1,24);
    x0 += k1; x1 += k2 + 4u;
    tfr(x0,x1,13); tfr(x0,x1,15); tfr(x0,x1,26); tfr(x0,x1,6);
    o0 = x0 + k2; o1 = x1 + k0 + 5u;
}
__device__ __forceinline__ uint2 tchild(uint2 k, uint32_t i) {
    uint32_t a, b; tf2(k.x, k.y, 0u, i, a, b); return make_uint2(a, b);
}
__device__ __forceinline__ float u01(uint2 k, uint32_t i) {
    uint32_t a, b; tf2(k.x, k.y, 0u, i, a, b);
    return __uint_as_float(((a ^ b) >> 9) | 0x3f800000u) - 1.0f;
}
__device__ __forceinline__ float gumbelf(uint2 k, uint32_t i) {   // exact (ray argmax)
    float f = u01(k, i);
    float u = fmaxf(TINYF, f + TINYF);
    return -logf(-logf(u));
}
// exponential race variable — EXACT logf mandatory (winners at u≈1, where
// __logf's ~1e-7 absolute error is ~100% relative error on the result).
__device__ __forceinline__ float expvarf(uint2 k, uint32_t i) {
    float f = u01(k, i);
    float u = fmaxf(TINYF, f + TINYF);
    return -logf(u);
}

// ---------- math ----------
__device__ __forceinline__ float sigmf(float x) { return 1.0f / (1.0f + expf(-x)); }
// fast softplus for the coarse MLP — rounds 12/15 proved (bit-identical failure
// norms) that its ~1e-5 logit perturbation flips ZERO categorical decisions.
__device__ __forceinline__ float softplus_fast(float x) {
    float t = __expf(-fabsf(x));
    return fmaxf(x, 0.0f) + __logf(1.0f + t);
}

// ---------- k0: keys + zero counts ----------
__global__ void k_init() {
    int t = threadIdx.x + blockIdx.x * blockDim.x;
    for (int i = t; i < NRAYC; i += gridDim.x * blockDim.x) g_cnts[i] = 0;
    if (t == 0) {
        uint2 root = make_uint2(0u, 42u);
        uint2 kc = tchild(root, 0), kf = tchild(root, 1);
        uint2 cA = tchild(kc, 0), cB = tchild(kc, 1);
        g_keys[0] = tchild(cA, 0); g_keys[1] = tchild(cA, 1); g_keys[2] = tchild(cB, 0);
        uint2 fA = tchild(kf, 0), fB = tchild(kf, 1);
        g_keys[3] = tchild(fA, 0); g_keys[4] = tchild(fA, 1); g_keys[5] = tchild(fA, 2);
        g_keys[6] = tchild(fA, 3); g_keys[7] = tchild(fA, 4);
        g_keys[8] = tchild(fB, 0); g_keys[9] = tchild(fB, 1); g_keys[10] = tchild(fB, 2);
    }
}

// ---------- k1: coarse (fast-softplus MLP; alpha/sigmoid path exact) ----------
__global__ void __launch_bounds__(128) k_coarse(
        const float* __restrict__ Rt, const float* __restrict__ W1,
        const float* __restrict__ b1, const float* __restrict__ w2,
        const float* __restrict__ b2v) {
    int r = blockIdx.x, v = blockIdx.y, t = threadIdx.x;
    int rayid = v * NRC + r;
    __shared__ float st[NPTS_C], sd[NPTS_C];
    __shared__ float W1s[192], b1s[64], w2s[64], dirs[3], org[3];
    for (int i = t; i < 192; i += 128) W1s[i] = W1[i];
    for (int i = t; i < 64; i += 128) { b1s[i] = b1[i]; w2s[i] = w2[i]; }
    if (t == 0) {
        float ru  = ((float)(r / 8) + u01(g_keys[0], (uint32_t)rayid)) / 64.0f;
        float rv  = ((float)(r % 8) + u01(g_keys[1], (uint32_t)rayid)) / 8.0f;
        float phi = ru * TWOPI;
        float ct = rv * (1.0f - MINCOS) + MINCOS;
        float snt = sqrtf(fmaxf(1.0f - ct * ct, 0.0f));
        float d0 = snt * cosf(phi), d1 = snt * sinf(phi), d2 = ct;
        const float* Rv = Rt + v * 12;
        for (int i = 0; i < 3; i++) {
            dirs[i] = d0 * Rv[i*4] + d1 * Rv[i*4+1] + d2 * Rv[i*4+2];
            org[i]  = Rv[i*4+3];
        }
    }
    {
        float eta = u01(g_keys[2], (uint32_t)(rayid * 128 + t)) * BINSZ;
        float left = BINSZ * (float)t;
        st[2*t] = left; st[2*t+1] = left + eta;
        if (t == 0) st[256] = BINSZ * 128.0f;
    }
    __syncthreads();
    float b2 = b2v[0];
    for (int k = t; k < NPTS_C; k += 128) {
        float s = st[k];
        float px = org[0] + s*dirs[0], py = org[1] + s*dirs[1], pz = org[2] + s*dirs[2];
        float acc = 0.0f;
        #pragma unroll 8
        for (int j = 0; j < HID; j++) {
            float z = fmaf(pz, W1s[128+j], fmaf(py, W1s[64+j], px * W1s[j])) + b1s[j];
            acc = fmaf(softplus_fast(z), w2s[j], acc);
        }
        sd[k] = acc + b2;
    }
    __syncthreads();
    for (int k = t; k < 256; k += 128) {
        float dl = st[k+1] - st[k];
        float ck = (sd[k+1] - sd[k]) / (dl + 1e-6f);
        float pv = (k > 0) ? (sd[k] - sd[k-1]) / ((st[k] - st[k-1]) + 1e-6f) : 0.0f;
        float c = fminf(fmaxf(fminf(pv, ck), -1000.0f), 0.0f);
        float ds = 0.5f * c * dl;
        float ms = 0.5f * (sd[k] + sd[k+1]);
        float pT = sigmf(64.0f * (ms - ds)), nT = sigmf(64.0f * (ms + ds));
        float mx = 0.5f*((org[0]+st[k]*dirs[0]) + (org[0]+st[k+1]*dirs[0]));
        float my = 0.5f*((org[1]+st[k]*dirs[1]) + (org[1]+st[k+1]*dirs[1]));
        float mz = 0.5f*((org[2]+st[k]*dirs[2]) + (org[2]+st[k+1]*dirs[2]));
        float nrm = sqrtf(mx*mx + my*my + mz*mz);
        float insf = (nrm < 1.0f && mz > 0.0f) ? 1.0f : 0.0f;
        g_al[(size_t)k * NRAYC + rayid] = (1.0f - nT / (pT + 1e-6f)) * insf;
    }
}

// ---------- k1b: coarse tail — 1 thread/ray, bit-exact sequential order ----------
__global__ void __launch_bounds__(128) k_coarse_tail(float* __restrict__ out) {
    int ray = blockIdx.x * blockDim.x + threadIdx.x;
    if (ray >= NRAYC) return;
    float T = 1.0f, rsum = 0.0f;
    float* spd = out + SP_OFF + (size_t)ray * NB;
    for (int b = 0; b < NB; b++) {
        float a0 = g_al[(size_t)(2*b)   * NRAYC + ray];
        float a1 = g_al[(size_t)(2*b+1) * NRAYC + ray];
        float w0 = a0 * T;
        float o0 = 1.0f - a0;   T *= o0*o0 + 1e-6f;
        float w1 = a1 * T;
        float o1 = 1.0f - a1;   T *= o1*o1 + 1e-6f;
        float sp = w0 + w1; spd[b] = sp; rsum += sp;
    }
    out[RP_OFF + (size_t)ray] = rsum;
}

// ---------- k2: ray categorical (exact) ----------
__global__ void __launch_bounds__(128) k_ray_idx(const float* __restrict__ out) {
    int p = blockIdx.x, v = blockIdx.y, t = threadIdx.x;
    const float* rp = out + RP_OFF + (size_t)v * NRC;
    uint2 kg = g_keys[5];
    float best = -3.4e38f; int bi = 1 << 30;
    for (int s = t; s < NRC; s += 128) {
        float val = gumbelf(kg, (uint32_t)((p * NVV + v) * NRC + s)) + logf(rp[s] + 1e-6f);
        if (val > best || (val == best && s < bi)) { best = val; bi = s; }
    }
    __shared__ float bv[128]; __shared__ int bx[128];
    bv[t] = best; bx[t] = bi; __syncthreads();
    for (int s = 64; s > 0; s >>= 1) {
        if (t < s) {
            if (bv[t+s] > bv[t] || (bv[t+s] == bv[t] && bx[t+s] < bx[t])) {
                bv[t] = bv[t+s]; bx[t] = bx[t+s];
            }
        }
        __syncthreads();
    }
    if (t == 0) {
        g_idx[v * NPDF_RAYS + p] = bx[0];
        atomicAdd(&g_cnts[v * NRC + bx[0]], 1);
    }
}

// ---------- k3: fine ray gen ----------
__global__ void __launch_bounds__(NRF) k_fine_rays(const float* __restrict__ Rt) {
    int v = blockIdx.x, r = threadIdx.x;
    int uv; float U1, U2;
    if (r < NRC) {
        uv = r;
        U1 = u01(g_keys[3], (uint32_t)(v * NRC + r));
        U2 = u01(g_keys[4], (uint32_t)(v * NRC + r));
    } else {
        int p = r - NRC;
        uv = g_idx[v * NPDF_RAYS + p];
        U1 = u01(g_keys[6], (uint32_t)(v * NPDF_RAYS + p));
        U2 = u01(g_keys[7], (uint32_t)(v * NPDF_RAYS + p));
    }
    float ru  = ((float)(uv / 8) + U1) / 64.0f;
    float rv  = ((float)(uv % 8) + U2) / 8.0f;
    float phi = ru * TWOPI;
    float ct = rv * (1.0f - MINCOS) + MINCOS;
    float snt = sqrtf(fmaxf(1.0f - ct * ct, 0.0f));
    float d0 = snt * cosf(phi), d1 = snt * sinf(phi), d2 = ct;
    const float* Rv = Rt + v * 12;
    size_t ray = (size_t)v * NRF + r;
    for (int i = 0; i < 3; i++)
        g_dir[ray*3+i] = d0*Rv[i*4] + d1*Rv[i*4+1] + d2*Rv[i*4+2];
    int cnt = g_cnts[v * NRC + uv];
    float sang = 2.0f * 3.14159265358979323846f * (1.0f - MINCOS);
    g_w[ray] = (1.0f / (((float)cnt + 1.0f) * 512.0f)) * ct * sang;
    g_uv[ray] = uv;
}

// ---------- k4: fine step sampling — exact race numerics (round-16 bits) ----------
__global__ void __launch_bounds__(128) k_fine_steps(const float* __restrict__ out) {
    int r = blockIdx.x, v = blockIdx.y, t = threadIdx.x;
    int lane = t & 31, wid = t >> 5;
    __shared__ float rinv[NB], base[NPTS_C], ex[NPDF_STEPS], exs[NPDF_STEPS];
    __shared__ int sbidx[NPDF_STEPS];
    int uv = g_uv[(size_t)v * NRF + r];
    rinv[t] = 1.0f / (out[SP_OFF + (size_t)(v * NRC + uv) * NB + t] + 1e-6f);
    {
        float eta = u01(g_keys[8], (uint32_t)((v * NRF + r) * 128 + t)) * BINSZ;
        float left = BINSZ * (float)t;
        base[2*t] = left; base[2*t+1] = left + eta;
        if (t == 0) base[256] = BINSZ * 128.0f;
    }
    __syncthreads();
    uint2 kg = g_keys[9];
    uint32_t ibase = (uint32_t)((uint32_t)v * NRF + (uint32_t)r) * 128u;
    for (int p = wid; p < NPDF_STEPS; p += 4) {
        uint32_t doff = (uint32_t)p * (uint32_t)(NVV * NRF) * 128u + ibase;
        float best = 3.4e38f; int bi = 1 << 30;
        #pragma unroll
        for (int q = 0; q < 4; q++) {
            int bin = lane + q * 32;
            float val = expvarf(kg, doff + (uint32_t)bin) * rinv[bin];
            if (val < best || (val == best && bin < bi)) { best = val; bi = bin; }
        }
        #pragma unroll
        for (int o = 16; o > 0; o >>= 1) {
            float v2 = __shfl_down_sync(0xffffffffu, best, o);
            int   i2 = __shfl_down_sync(0xffffffffu, bi, o);
            if (v2 < best || (v2 == best && i2 < bi)) { best = v2; bi = i2; }
        }
        if (lane == 0) sbidx[p] = bi;
    }
    __syncthreads();
    if (t < NPDF_STEPS)
        ex[t] = BINSZ * (float)sbidx[t] + u01(g_keys[10], (uint32_t)((v * NRF + r) * 32 + t)) * BINSZ;
    __syncthreads();
    if (t < NPDF_STEPS) {
        float x = ex[t]; int rank = 0;
        #pragma unroll
        for (int j = 0; j < NPDF_STEPS; j++) {
            float y = ex[j];
            rank += (y < x) || (y == x && j < t);
        }
        exs[rank] = x;
    }
    __syncthreads();
    float* dst = g_steps + ((size_t)v * NRF + r) * NPTS_F;
    for (int k = t; k < NPTS_C; k += 128) {
        float x = base[k]; int lo = 0, hi = NPDF_STEPS;
        while (lo < hi) { int m = (lo+hi)>>1; if (exs[m] < x) lo = m+1; else hi = m; }
        dst[k + lo] = x;
    }
    if (t < NPDF_STEPS) {
        float x = exs[t]; int lo = 0, hi = NPTS_C;
        while (lo < hi) { int m = (lo+hi)>>1; if (base[m] <= x) lo = m+1; else hi = m; }
        dst[t + lo] = x;
    }
}

// ---------- k5: fine main — fast transcendentals + parallel scan/scatter ----------
__global__ void __launch_bounds__(96) k_fine_main(
        const float* __restrict__ Rt, const float* __restrict__ W1,
        const float* __restrict__ b1, const float* __restrict__ w2,
        const float* __restrict__ b2v, const float* __restrict__ inv_sv,
        const float* __restrict__ rhov, float* __restrict__ out) {
    int r = blockIdx.x, v = blockIdx.y, t = threadIdx.x;
    int lane = t & 31, wid = t >> 5;
    __shared__ float W1s[192], b1s[64], w2s[64];
    __shared__ float al[NPF], rf[NPF], Ts[NPF];
    __shared__ int bidxs[NPF];
    __shared__ unsigned char vfl[NPF];
    __shared__ float wtot[3];
    __shared__ float bwv[NB];
    for (int i = t; i < 192; i += 96) W1s[i] = W1[i];
    for (int i = t; i < 64; i += 96) { b1s[i] = b1[i]; w2s[i] = w2[i]; }
    size_t ray = (size_t)v * NRF + r;
    const float* se = g_steps + ray * NPTS_F;
    float dx = g_dir[ray*3], dy = g_dir[ray*3+1], dz = g_dir[ray*3+2];
    const float* Rv = Rt + v * 12;
    float ox = Rv[3], oy = Rv[7], oz = Rv[11];
    float b2 = b2v[0], inv_s = inv_sv[0], rho = rhov[0];
    __syncthreads();
    for (int k = t; k < NPF; k += 96) {
        float s0 = se[k], s1 = se[k+1];
        float delta = s1 - s0, sm = 0.5f * (s1 + s0);
        float px = ox + sm*dx, py = oy + sm*dy, pz = oz + sm*dz;
        float nrm = sqrtf(px*px + py*py + pz*pz);
        float insf = (nrm < 1.0f && pz > 0.0f) ? 1.0f : 0.0f;
        float sdf = 0.0f, n0 = 0.0f, n1 = 0.0f, n2 = 0.0f;
        #pragma unroll 8
        for (int j = 0; j < HID; j++) {
            float w0j = W1s[j], w1j = W1s[64+j], w2j = W1s[128+j];
            float z = fmaf(pz, w2j, fmaf(py, w1j, px * w0j)) + b1s[j];
            float tE = __expf(-fabsf(z));
            sdf = fmaf(fmaxf(z, 0.0f) + __logf(1.0f + tE), w2s[j], sdf);
            float inv = __fdividef(1.0f, 1.0f + tE);
            float sg = ((z >= 0.0f) ? inv : tE * inv) * w2s[j];
            n0 = fmaf(sg, w0j, n0); n1 = fmaf(sg, w1j, n1); n2 = fmaf(sg, w2j, n2);
        }
        sdf = (sdf + b2) * insf; n0 *= insf; n1 *= insf; n2 *= insf;
        out[SDF_OFF + ray*NPF + k] = sdf;
        out[NORM_OFF + (ray*NPF + k)*3 + 0] = n0;
        out[NORM_OFF + (ray*NPF + k)*3 + 1] = n1;
        out[NORM_OFF + (ray*NPF + k)*3 + 2] = n2;
        float cs = dx*n0 + dy*n1 + dz*n2;
        float ac = -fmaxf(fmaf(cs, -0.5f, 0.5f), 0.0f);
        float ds = 0.5f * ac * delta;
        float argp = inv_s * (sdf - ds), argn = inv_s * (sdf + ds);
        float pT = __fdividef(1.0f, 1.0f + __expf(-argp));
        float nT = __fdividef(1.0f, 1.0f + __expf(-argn));
        float a = (1.0f - nT / (pT + 1e-6f)) * insf;
        out[ALPHA_OFF + ray*NPF + k] = a;
        al[k] = a;
        rf[k] = rho * (-ac * __fdividef(1.0f, sm*sm + 1e-6f));
        int bi = (int)floorf(sm / BINSZ);
        bi = max(0, min(NB - 1, bi));
        bool valid = (sm > (float)bi * BINSZ) && (sm < (float)(bi+1) * BINSZ);
        bidxs[k] = bi;
        vfl[k] = valid ? 1 : 0;
    }
    __syncthreads();
    {
        float a0 = al[3*t], a1 = al[3*t+1], a2 = al[3*t+2];
        float q0 = (1.0f - a0) * (1.0f - a0);
        float q1 = (1.0f - a1) * (1.0f - a1);
        float q2 = (1.0f - a2) * (1.0f - a2);
        float loc = q0 * q1 * q2;
        float inc = loc;
        #pragma unroll
        for (int o = 1; o < 32; o <<= 1) {
            float u = __shfl_up_sync(0xffffffffu, inc, o);
            if (lane >= o) inc *= u;
        }
        float exc = __shfl_up_sync(0xffffffffu, inc, 1);
        if (lane == 0) exc = 1.0f;
        if (lane == 31) wtot[wid] = inc;
        __syncthreads();
        float off = 1.0f;
        if (wid >= 1) off *= wtot[0];
        if (wid >= 2) off *= wtot[1];
        float P = off * exc;
        Ts[3*t]   = P;
        Ts[3*t+1] = P * q0;
        Ts[3*t+2] = P * q0 * q1;
    }
    __syncthreads();
    for (int k = t; k < NPF; k += 96) {
        out[T_OFF + ray*NPF + k] = Ts[k];
        out[W_OFF + ray*NPF + k] = al[k] * Ts[k];
    }
    for (int b = t; b < NB; b += 96) {
        int lo = 0, hi = NPF;
        while (lo < hi) { int m = (lo+hi)>>1; if (bidxs[m] < b) lo = m+1; else hi = m; }
        float ba = 0.0f, bw = 0.0f, br = 0.0f;
        for (int k = lo; k < NPF && bidxs[k] == b; k++) {
            if (vfl[k]) {
                float wk = al[k] * Ts[k];
                ba += al[k]; bw += wk; br += wk * rf[k];
            }
        }
        out[BA_OFF + ray*NB + b] = ba;
        out[BW_OFF + ray*NB + b] = bw;
        g_radbins[ray*NB + b] = br;
        bwv[b] = bw;
    }
    __syncthreads();
    if (wid == 0) {
        float s = bwv[lane] + bwv[lane+32] + bwv[lane+64] + bwv[lane+96];
        #pragma unroll
        for (int o = 16; o > 0; o >>= 1) s += __shfl_down_sync(0xffffffffu, s, o);
        if (lane == 0) out[OP_OFF + ray] = s;
    }
}

// ---------- k6: hists ----------
__global__ void __launch_bounds__(NB) k_hists(float* __restrict__ out) {
    int v = blockIdx.x, b = threadIdx.x;
    float acc = 0.0f;
    for (int r = 0; r < NRF; r++)
        acc += g_radbins[((size_t)v * NRF + r) * NB + b] * g_w[v * NRF + r];
    out[HIST_OFF + (size_t)v * NB + b] = acc;
}

extern "C" void kernel_launch(void* const* d_in, const int* in_sizes, int n_in,
                              void* d_out, int out_size) {
    const float* Rt = (const float*)d_in[0];
    const float* W1 = (const float*)d_in[1];
    const float* b1 = (const float*)d_in[2];
    const float* w2 = (const float*)d_in[3];
    const float* b2 = (const float*)d_in[4];
    const float* inv_s = (const float*)d_in[5];
    const float* rho = (const float*)d_in[6];
    float* out = (float*)d_out;
    k_init<<<64, 256>>>();
    k_coarse<<<dim3(NRC, NVV), 128>>>(Rt, W1, b1, w2, b2);
    k_coarse_tail<<<NRAYC / 128, 128>>>(out);
    k_ray_idx<<<dim3(NPDF_RAYS, NVV), 128>>>(out);
    k_fine_rays<<<NVV, NRF>>>(Rt);
    k_fine_steps<<<dim3(NRF, NVV), 128>>>(out);
    k_fine_main<<<dim3(NRF, NVV), 96>>>(Rt, W1, b1, w2, b2, inv_s, rho, out);
    k_hists<<<NVV, NB>>>(out);
}